// round 14
// baseline (speedup 1.0000x reference)
#include <cuda_runtime.h>
#include <cuda_bf16.h>
#include <cstdint>

#define BB 8
#define NN 4096
#define NP (BB*NN)
#define KK 20

typedef unsigned long long ull;
typedef unsigned short ushort_t;

__device__ __forceinline__ ull pk2(float a, float b){ ull r; asm("mov.b64 %0, {%1,%2};" : "=l"(r) : "f"(a), "f"(b)); return r; }
__device__ __forceinline__ ull fma2(ull a, ull b, ull c){ ull d; asm("fma.rn.f32x2 %0, %1, %2, %3;" : "=l"(d) : "l"(a), "l"(b), "l"(c)); return d; }
__device__ __forceinline__ void upk(ull v, float& a, float& b){ asm("mov.b64 {%0,%1}, %2;" : "=f"(a), "=f"(b) : "l"(v)); }

__device__ __forceinline__ uint32_t smem_u32(const void* p) {
    uint32_t a;
    asm("{ .reg .u64 tmp; cvta.to.shared.u64 tmp, %1; cvt.u32.u64 %0, tmp; }" : "=r"(a) : "l"(p));
    return a;
}
__device__ __forceinline__ void ldmx4(uint32_t* r, uint32_t addr) {
    asm volatile("ldmatrix.sync.aligned.m8n8.x4.shared.b16 {%0,%1,%2,%3}, [%4];"
        : "=r"(r[0]), "=r"(r[1]), "=r"(r[2]), "=r"(r[3]) : "r"(addr));
}
__device__ __forceinline__ void mma16816(float* d, const uint32_t* a, const uint32_t* b) {
    asm volatile("mma.sync.aligned.m16n8k16.row.col.f32.bf16.bf16.f32 "
        "{%0,%1,%2,%3}, {%4,%5,%6,%7}, {%8,%9}, {%0,%1,%2,%3};"
        : "+f"(d[0]), "+f"(d[1]), "+f"(d[2]), "+f"(d[3])
        : "r"(a[0]), "r"(a[1]), "r"(a[2]), "r"(a[3]), "r"(b[0]), "r"(b[1]));
}
__device__ __forceinline__ void bf16split(float v, __nv_bfloat16& h, __nv_bfloat16& l) {
    h = __float2bfloat16_rn(v);
    l = __float2bfloat16_rn(v - __bfloat162float(h));
}

// ---------------- scratch -------------------------------------------------------
__device__ float d_h[NP*64];
__device__ __nv_bfloat16 d_hh[NP*64];
__device__ __nv_bfloat16 d_hl[NP*64];
__device__ float d_hsq[NP];
__device__ float d_xsq[NP];
__device__ int   d_idx1[NP*KK];
__device__ int   d_idx2[NP*KK];
__device__ float d_A1[NP*128];
__device__ float d_C1[NP*128];
__device__ float d_A3[(size_t)NP*256];
__device__ float d_C3[(size_t)NP*256];
__device__ __nv_bfloat16 d_cath[(size_t)NP*512];
__device__ __nv_bfloat16 d_catl[(size_t)NP*512];
__device__ __nv_bfloat16 d_w3h[1024*512];
__device__ __nv_bfloat16 d_w3l[1024*512];
__device__ __nv_bfloat16 d_wsnh[512*128];
__device__ __nv_bfloat16 d_wsnl[512*128];

// ================= phase 1 bodies ===============================================
__device__ void mlp_body(int blk,
    const float* __restrict__ x, const float* __restrict__ w1, const float* __restrict__ b1,
    const float* __restrict__ w2, const float* __restrict__ b2)
{
    __shared__ float w1s[192], b1s[64], b2s[64], w2s[4096];
    int t = threadIdx.x;
    for (int i = t; i < 192; i += 256) w1s[i] = w1[i];
    if (t < 64) { b1s[t] = b1[t]; b2s[t] = b2[t]; }
    for (int i = t; i < 4096; i += 256) w2s[i] = w2[i];
    __syncthreads();
    int pt = blk * 256 + t;
    float x0 = x[pt*3+0], x1 = x[pt*3+1], x2 = x[pt*3+2];
    d_xsq[pt] = x0*x0 + x1*x1 + x2*x2;
    float h1[64];
#pragma unroll
    for (int o = 0; o < 64; o++) {
        float a = b1s[o] + w1s[o*3]*x0 + w1s[o*3+1]*x1 + w1s[o*3+2]*x2;
        h1[o] = fmaxf(a, 0.f);
    }
    float sq = 0.f;
#pragma unroll 2
    for (int o = 0; o < 64; o++) {
        float a = b2s[o];
#pragma unroll
        for (int c = 0; c < 64; c++) a += w2s[o*64+c] * h1[c];
        a = fmaxf(a, 0.f);
        d_h[(size_t)pt*64 + o] = a;
        __nv_bfloat16 h, l; bf16split(a, h, l);
        d_hh[(size_t)pt*64 + o] = h;
        d_hl[(size_t)pt*64 + o] = l;
        sq += a*a;
    }
    d_hsq[pt] = sq;
}

__device__ void cvt_split_body(int blk, const float* __restrict__ src,
    __nv_bfloat16* __restrict__ hi, __nv_bfloat16* __restrict__ lo)
{
    int i = (blk * 256 + threadIdx.x) * 4;
    float4 v = *(const float4*)&src[i];
    __nv_bfloat16 h0, h1, h2, h3, l0, l1, l2, l3;
    bf16split(v.x, h0, l0); bf16split(v.y, h1, l1);
    bf16split(v.z, h2, l2); bf16split(v.w, h3, l3);
    __nv_bfloat162* hp = (__nv_bfloat162*)&hi[i];
    __nv_bfloat162* lp = (__nv_bfloat162*)&lo[i];
    hp[0] = __nv_bfloat162(h0, h1); hp[1] = __nv_bfloat162(h2, h3);
    lp[0] = __nv_bfloat162(l0, l1); lp[1] = __nv_bfloat162(l2, l3);
}

__device__ void wsn_split_body(int blk, const float* __restrict__ wsn1,
    __nv_bfloat16* __restrict__ wh, __nv_bfloat16* __restrict__ wl)
{
    int i = blk * 256 + threadIdx.x;
    int o = i >> 7, c = i & 127;
    float va = wsn1[o*256 + c];
    float vb = wsn1[o*256 + 128 + c];
    __nv_bfloat16 h, l;
    bf16split(va, h, l);
    wh[o*128 + c] = h; wl[o*128 + c] = l;
    bf16split(vb - va, h, l);
    wh[(256 + o)*128 + c] = h; wl[(256 + o)*128 + c] = l;
}

__global__ __launch_bounds__(256) void phase1_kernel(
    const float* __restrict__ x, const float* __restrict__ w1, const float* __restrict__ b1,
    const float* __restrict__ w2, const float* __restrict__ b2,
    const float* __restrict__ w3, const float* __restrict__ wsn1)
{
    int blk = blockIdx.x;
    if (blk < 128)      mlp_body(blk, x, w1, b1, w2, b2);
    else if (blk < 640) cvt_split_body(blk - 128, w3, d_w3h, d_w3l);
    else                wsn_split_body(blk - 640, wsn1, d_wsnh, d_wsnl);
}

// ================= phase 2 bodies ===============================================
// ---- knn64 via mma (staged ds, gated scan, consolidated rebuild) ----
#define KM_QPAD 72
#define KM_QH 0
#define KM_QL (64*KM_QPAD*2)
#define KM_CH (2*64*KM_QPAD*2)
#define KM_CL (3*64*KM_QPAD*2)
#define KM_QXX (4*64*KM_QPAD*2)
#define KM_CXX (KM_QXX + 256)
#define KM_DS  (KM_CXX + 256)
#define KM_SV  (KM_DS + 64*68*4)
#define KM_BV  (KM_SV + 20*256*4)
#define KM_SI  (KM_BV + 16*256*4)
#define KM_BI  (KM_SI + 20*256*2)
#define KM_SMEM (KM_BI + 16*256*2)

__device__ void knn64_body(char* kms, int blk,
    const __nv_bfloat16* __restrict__ hh, const __nv_bfloat16* __restrict__ hl,
    const float* __restrict__ sq, int* __restrict__ out)
{
    const int QT = 64, CT = 64;
    __nv_bfloat16* qh = (__nv_bfloat16*)(kms + KM_QH);
    __nv_bfloat16* ql = (__nv_bfloat16*)(kms + KM_QL);
    __nv_bfloat16* ch = (__nv_bfloat16*)(kms + KM_CH);
    __nv_bfloat16* cl = (__nv_bfloat16*)(kms + KM_CL);
    float* qxx = (float*)(kms + KM_QXX);
    float* cxx = (float*)(kms + KM_CXX);
    float* ds  = (float*)(kms + KM_DS);
    float* sv  = (float*)(kms + KM_SV);
    float* bv  = (float*)(kms + KM_BV);
    ushort_t* si = (ushort_t*)(kms + KM_SI);
    ushort_t* bi = (ushort_t*)(kms + KM_BI);

    int b  = blk / (NN/QT);
    int q0 = (blk % (NN/QT)) * QT;
    int t = threadIdx.x, lane = t & 31, warp = t >> 5;
    int qq = t >> 2, s = t & 3;
    int wm = warp & 3, wn = warp >> 2;
    int a_row = wm*16 + (lane & 15), a_col = (lane >> 4) * 8;
    int b_row = wn*32 + (lane & 7) + ((lane >> 4) ? 8 : 0);
    int b_col = ((lane >> 3) & 1) * 8;
    uint32_t uQh = smem_u32(qh), uQl = smem_u32(ql);
    uint32_t uCh = smem_u32(ch), uCl = smem_u32(cl);

    for (int i = t; i < 64*8; i += 256) {
        int r = i >> 3, c = (i & 7) * 8;
        size_t gi = (size_t)(b*NN + q0 + r)*64 + c;
        *(uint4*)&qh[r*KM_QPAD + c] = *(const uint4*)&hh[gi];
        *(uint4*)&ql[r*KM_QPAD + c] = *(const uint4*)&hl[gi];
    }
    if (t < QT) qxx[t] = sq[b*NN + q0 + t];

#pragma unroll
    for (int r = 0; r < KK; r++) { sv[r*256 + t] = -3.4e38f; si[r*256 + t] = 0xFFFF; }
    float minv = -3.4e38f; int minp = 0;
    float gthr = -3.4e38f;

    for (int tile = 0; tile < NN/CT; tile++) {
        __syncthreads();
        for (int i = t; i < 64*8; i += 256) {
            int r = i >> 3, c = (i & 7) * 8;
            size_t gi = (size_t)(b*NN + tile*CT + r)*64 + c;
            *(uint4*)&ch[r*KM_QPAD + c] = *(const uint4*)&hh[gi];
            *(uint4*)&cl[r*KM_QPAD + c] = *(const uint4*)&hl[gi];
        }
        if (t < CT) cxx[t] = sq[b*NN + tile*CT + t];
        __syncthreads();

        float acc[4][4];
#pragma unroll
        for (int ni = 0; ni < 4; ni++)
#pragma unroll
            for (int e = 0; e < 4; e++) acc[ni][e] = 0.f;
#pragma unroll
        for (int ks = 0; ks < 4; ks++) {
            int k0 = ks * 16;
            uint32_t ah[4], al[4];
            uint32_t offA = (uint32_t)((a_row*KM_QPAD + a_col + k0) * 2);
            ldmx4(ah, uQh + offA);
            ldmx4(al, uQl + offA);
#pragma unroll
            for (int j = 0; j < 2; j++) {
                uint32_t bh[4], bl[4];
                uint32_t offB = (uint32_t)(((b_row + j*16)*KM_QPAD + b_col + k0) * 2);
                ldmx4(bh, uCh + offB);
                ldmx4(bl, uCl + offB);
#pragma unroll
                for (int sub = 0; sub < 2; sub++) {
                    int ni = j*2 + sub;
                    mma16816(acc[ni], ah, bh + sub*2);
                    mma16816(acc[ni], ah, bl + sub*2);
                    mma16816(acc[ni], al, bh + sub*2);
                }
            }
        }
        {
            int r = lane >> 2, c2 = (lane & 3) * 2;
            int row0 = wm*16 + r, row1 = row0 + 8;
            float qx0 = qxx[row0], qx1 = qxx[row1];
#pragma unroll
            for (int ni = 0; ni < 4; ni++) {
                int col = wn*32 + ni*8 + c2;
                float cx0 = cxx[col], cx1 = cxx[col+1];
                float2 v0, v1;
                v0.x = 2.f*acc[ni][0] - qx0 - cx0; v0.y = 2.f*acc[ni][1] - qx0 - cx1;
                v1.x = 2.f*acc[ni][2] - qx1 - cx0; v1.y = 2.f*acc[ni][3] - qx1 - cx1;
                *(float2*)&ds[row0*68 + col] = v0;
                *(float2*)&ds[row1*68 + col] = v1;
            }
        }
        __syncthreads();

        int cnt = 0;
        const float* row = &ds[qq*68 + s*16];
        int base = tile*CT + s*16;
#pragma unroll
        for (int c4 = 0; c4 < 4; c4++) {
            float4 v = *(const float4*)&row[c4*4];
            float m = fmaxf(fmaxf(v.x, v.y), fmaxf(v.z, v.w));
            if (m > gthr) {
                int id0 = base + c4*4;
                if (v.x > gthr) { bv[cnt*256+t] = v.x; bi[cnt*256+t] = (ushort_t)(id0  ); cnt++; }
                if (v.y > gthr) { bv[cnt*256+t] = v.y; bi[cnt*256+t] = (ushort_t)(id0+1); cnt++; }
                if (v.z > gthr) { bv[cnt*256+t] = v.z; bi[cnt*256+t] = (ushort_t)(id0+2); cnt++; }
                if (v.w > gthr) { bv[cnt*256+t] = v.w; bi[cnt*256+t] = (ushort_t)(id0+3); cnt++; }
            }
        }
        for (int j = 0; __any_sync(0xffffffffu, j < cnt); j++) {
            if (j < cnt) {
                float d = bv[j*256+t];
                if (d > minv) {
                    sv[minp*256+t] = d; si[minp*256+t] = bi[j*256+t];
                    float mv = sv[t]; int mp = 0;
#pragma unroll
                    for (int r = 1; r < KK; r++) {
                        float x = sv[r*256+t];
                        if (x < mv) { mv = x; mp = r; }
                    }
                    minv = mv; minp = mp;
                }
            }
        }
        float m = minv;
        m = fmaxf(m, __shfl_xor_sync(0xffffffffu, m, 1));
        m = fmaxf(m, __shfl_xor_sync(0xffffffffu, m, 2));
        gthr = m;
    }

#pragma unroll 1
    for (int r = 0; r < KK; r++) {
        float bvv = -3.4e38f; int bid = 0x7fffffff; int bslot = 0;
#pragma unroll
        for (int rr = 0; rr < KK; rr++) {
            float x = sv[rr*256+t]; int xi = si[rr*256+t];
            bool better = (x > bvv) || (x == bvv && xi < bid);
            if (better) { bvv = x; bid = xi; bslot = rr; }
        }
        float v = bvv; int id = bid; int sl = s;
#pragma unroll
        for (int off = 1; off <= 2; off <<= 1) {
            float ov = __shfl_xor_sync(0xffffffffu, v, off);
            int  oid = __shfl_xor_sync(0xffffffffu, id, off);
            int  osl = __shfl_xor_sync(0xffffffffu, sl, off);
            if (ov > v || (ov == v && oid < id)) { v = ov; id = oid; sl = osl; }
        }
        if (sl == s) sv[bslot*256+t] = -3.4e38f;
        if (s == 0) out[((size_t)(b*NN + q0 + qq))*KK + r] = id;
    }
}

// ---- knn small-C (f32x2, staged ds, gated scan) ----
template<int C>
__device__ void knn_small_body(float* km, int blk,
    const float* __restrict__ data, const float* __restrict__ sq, int* __restrict__ out)
{
    const int QT = 64, CT = 64;
    const int QDUP_F = (C*130 + 3) & ~3;
    ull*   qdup = (ull*)km;
    float* csT  = km + QDUP_F;
    float* ds   = csT + C*68;
    float* qxx  = ds + 64*68;
    float* cxx  = qxx + 64;
    float* sv   = cxx + 64;
    float* bv   = sv + 20*256;
    ushort_t* si = (ushort_t*)(bv + 16*256);
    ushort_t* bi = si + 20*256;

    int b  = blk / (NN/QT);
    int q0 = (blk % (NN/QT)) * QT;
    int t = threadIdx.x;
    int tq = t >> 4, tc = t & 15;
    int qq = t >> 2, s = t & 3;

    for (int i = t; i < QT*C; i += 256) {
        int q = i / C, d = i - q*C;
        float v = data[((size_t)(b*NN + q0 + q))*C + d];
        qdup[d*65 + q] = pk2(v, v);
    }
    if (t < QT) qxx[t] = sq[b*NN + q0 + t];

#pragma unroll
    for (int r = 0; r < KK; r++) { sv[r*256 + t] = -3.4e38f; si[r*256 + t] = 0xFFFF; }
    float minv = -3.4e38f; int minp = 0;
    float gthr = -3.4e38f;

    for (int tile = 0; tile < NN/CT; tile++) {
        __syncthreads();
        for (int i = t; i < CT*C; i += 256) {
            int cth = i / C, d = i - cth*C;
            csT[d*68 + cth] = data[((size_t)(b*NN + tile*CT + cth))*C + d];
        }
        if (t < CT) cxx[t] = sq[b*NN + tile*CT + t];
        __syncthreads();

        ull a00=0,a01=0,a10=0,a11=0,a20=0,a21=0,a30=0,a31=0;
#pragma unroll 8
        for (int k = 0; k < C; k++) {
            ulonglong2 cp = *(const ulonglong2*)&csT[k*68 + tc*4];
            const ull* qd = &qdup[k*65 + tq*4];
            ull q0d = qd[0], q1d = qd[1], q2d = qd[2], q3d = qd[3];
            a00 = fma2(q0d, cp.x, a00); a01 = fma2(q0d, cp.y, a01);
            a10 = fma2(q1d, cp.x, a10); a11 = fma2(q1d, cp.y, a11);
            a20 = fma2(q2d, cp.x, a20); a21 = fma2(q2d, cp.y, a21);
            a30 = fma2(q3d, cp.x, a30); a31 = fma2(q3d, cp.y, a31);
        }
        float cx0 = cxx[tc*4], cx1 = cxx[tc*4+1], cx2 = cxx[tc*4+2], cx3 = cxx[tc*4+3];
        ull accs[4][2] = {{a00,a01},{a10,a11},{a20,a21},{a30,a31}};
#pragma unroll
        for (int i = 0; i < 4; i++) {
            float qx = qxx[tq*4 + i];
            float d0, d1, d2, d3;
            upk(accs[i][0], d0, d1); upk(accs[i][1], d2, d3);
            float4 r;
            r.x = 2.f*d0 - qx - cx0; r.y = 2.f*d1 - qx - cx1;
            r.z = 2.f*d2 - qx - cx2; r.w = 2.f*d3 - qx - cx3;
            *(float4*)&ds[(tq*4 + i)*68 + tc*4] = r;
        }
        __syncthreads();

        int cnt = 0;
        const float* row = &ds[qq*68 + s*16];
        int base = tile*CT + s*16;
#pragma unroll
        for (int c4 = 0; c4 < 4; c4++) {
            float4 v = *(const float4*)&row[c4*4];
            float m = fmaxf(fmaxf(v.x, v.y), fmaxf(v.z, v.w));
            if (m > gthr) {
                int id0 = base + c4*4;
                if (v.x > gthr) { bv[cnt*256+t] = v.x; bi[cnt*256+t] = (ushort_t)(id0  ); cnt++; }
                if (v.y > gthr) { bv[cnt*256+t] = v.y; bi[cnt*256+t] = (ushort_t)(id0+1); cnt++; }
                if (v.z > gthr) { bv[cnt*256+t] = v.z; bi[cnt*256+t] = (ushort_t)(id0+2); cnt++; }
                if (v.w > gthr) { bv[cnt*256+t] = v.w; bi[cnt*256+t] = (ushort_t)(id0+3); cnt++; }
            }
        }
        for (int j = 0; __any_sync(0xffffffffu, j < cnt); j++) {
            if (j < cnt) {
                float d = bv[j*256+t];
                if (d > minv) {
                    sv[minp*256+t] = d; si[minp*256+t] = bi[j*256+t];
                    float mv = sv[t]; int mp = 0;
#pragma unroll
                    for (int r = 1; r < KK; r++) {
                        float x = sv[r*256+t];
                        if (x < mv) { mv = x; mp = r; }
                    }
                    minv = mv; minp = mp;
                }
            }
        }
        float m = minv;
        m = fmaxf(m, __shfl_xor_sync(0xffffffffu, m, 1));
        m = fmaxf(m, __shfl_xor_sync(0xffffffffu, m, 2));
        gthr = m;
    }

#pragma unroll 1
    for (int r = 0; r < KK; r++) {
        float bvv = -3.4e38f; int bid = 0x7fffffff; int bslot = 0;
#pragma unroll
        for (int rr = 0; rr < KK; rr++) {
            float x = sv[rr*256+t]; int xi = si[rr*256+t];
            bool better = (x > bvv) || (x == bvv && xi < bid);
            if (better) { bvv = x; bid = xi; bslot = rr; }
        }
        float v = bvv; int id = bid; int sl = s;
#pragma unroll
        for (int off = 1; off <= 2; off <<= 1) {
            float ov = __shfl_xor_sync(0xffffffffu, v, off);
            int  oid = __shfl_xor_sync(0xffffffffu, id, off);
            int  osl = __shfl_xor_sync(0xffffffffu, sl, off);
            if (ov > v || (ov == v && oid < id)) { v = ov; id = oid; sl = osl; }
        }
        if (sl == s) sv[bslot*256+t] = -3.4e38f;
        if (s == 0) out[((size_t)(b*NN + q0 + qq))*KK + r] = id;
    }
}

// ---- precomp64 (f32x2) ----
__device__ void precomp64_body(float* sm, int blk, int nblk,
    const float* __restrict__ in,
    const float* __restrict__ W, const float* __restrict__ bias,
    float* __restrict__ A, float* __restrict__ Cc)
{
    const int CIN = 64;
    float* wa = sm;
    float* wd = sm + CIN*128;
    ull* invd = (ull*)(sm + 2*CIN*128);
    int t = threadIdx.x;
    int to = t & 31, rr = (t >> 5) & 1, pp = t >> 6;
    int o4 = 4*to;

    for (int i = t; i < 128*2*CIN; i += 256) {
        int oo = i / (2*CIN), c = i - oo*(2*CIN);
        float v = W[i];
        if (c < CIN) wa[c*128 + oo] = v; else wd[(c-CIN)*128 + oo] = v;
    }
    __syncthreads();
    for (int i = t; i < CIN*128; i += 256) wd[i] -= wa[i];
    ull bb0 = 0, bb1 = 0;
    if (rr) { bb0 = pk2(bias[o4], bias[o4+1]); bb1 = pk2(bias[o4+2], bias[o4+3]); }
    const float* src = rr ? wd : wa;
    float* dst = rr ? Cc : A;
    __syncthreads();

    for (int grp = blk; grp < NP/8; grp += nblk) {
        __syncthreads();
        for (int i = t; i < 8*CIN; i += 256) {
            int c = i & (CIN-1), p = i >> 6;
            float v = in[(size_t)(grp*8 + p)*64 + c];
            invd[c*8 + p] = pk2(v, v);
        }
        __syncthreads();
        ull acc[2][2] = {{bb0, bb1}, {bb0, bb1}};
#pragma unroll 4
        for (int c = 0; c < CIN; c++) {
            ulonglong2 wp = *(const ulonglong2*)&src[c*128 + o4];
            ull iv0 = invd[c*8 + 2*pp], iv1 = invd[c*8 + 2*pp + 1];
            acc[0][0] = fma2(wp.x, iv0, acc[0][0]);
            acc[0][1] = fma2(wp.y, iv0, acc[0][1]);
            acc[1][0] = fma2(wp.x, iv1, acc[1][0]);
            acc[1][1] = fma2(wp.y, iv1, acc[1][1]);
        }
#pragma unroll
        for (int pt = 0; pt < 2; pt++) {
            size_t base = (size_t)(grp*8 + 2*pp + pt)*128 + o4;
            *(ull*)&dst[base]     = acc[pt][0];
            *(ull*)&dst[base + 2] = acc[pt][1];
        }
    }
}

// interleaved dispatch: precomp first, then knn64/knn3 alternating
__global__ __launch_bounds__(256, 2) void phase2_kernel(
    const float* __restrict__ x,
    const float* __restrict__ wdg1, const float* __restrict__ bdg1)
{
    extern __shared__ char dsm[];
    int blk = blockIdx.x;
    if (blk < 148) {
        precomp64_body((float*)dsm, blk, 148, d_h, wdg1, bdg1, d_A1, d_C1);
    } else {
        int i = blk - 148;
        if (i & 1) knn_small_body<3>((float*)dsm, i >> 1, x, d_xsq, d_idx2);
        else       knn64_body(dsm, i >> 1, d_hh, d_hl, d_hsq, d_idx1);
    }
}

// ---------------- kernel 4: fused edge-conv1 + edge-conv2 via mma.sync -----------
#define E2_CPAD 136
#define E2_SPAD 132
#define E2_WH 0
#define E2_WL (128*E2_CPAD*2)
#define E2_G  (E2_WL + 128*E2_CPAD*2)
#define E2_GL_OFF (160*E2_CPAD*2)
#define E2_C1 (E2_G + 2*160*E2_CPAD*2)
#define E2_PX1 (E2_C1 + 1024*4)
#define E2_B2 (E2_PX1 + 4096*4)
#define E2_IXS (E2_B2 + 512)
#define E2_SMEM (E2_IXS + 640)

__global__ __launch_bounds__(256) void edge2_kernel(
    const float* __restrict__ A1, const float* __restrict__ C1,
    const int* __restrict__ idx, const float* __restrict__ w2,
    const float* __restrict__ b2,
    __nv_bfloat16* __restrict__ cath, __nv_bfloat16* __restrict__ catl)
{
    extern __shared__ char esm[];
    __nv_bfloat16* wh = (__nv_bfloat16*)(esm + E2_WH);
    __nv_bfloat16* wl = (__nv_bfloat16*)(esm + E2_WL);
    __nv_bfloat16* gh = (__nv_bfloat16*)(esm + E2_G);
    __nv_bfloat16* gl = (__nv_bfloat16*)(esm + E2_G + E2_GL_OFF);
    float* stage = (float*)(esm + E2_G);
    float* c1s = (float*)(esm + E2_C1);
    float* px1 = (float*)(esm + E2_PX1);
    float* b2s = (float*)(esm + E2_B2);
    int*   ixs = (int*)(esm + E2_IXS);

    int t = threadIdx.x, lane = t & 31, warp = t >> 5;
    for (int i = t; i < 128*128; i += 256) {
        float v = w2[i];
        __nv_bfloat16 h, l; bf16split(v, h, l);
        int o = i >> 7, c = i & 127;
        wh[o*E2_CPAD + c] = h; wl[o*E2_CPAD + c] = l;
    }
    if (t < 128) b2s[t] = b2[t];
    __syncthreads();

    int cc  = t & 127, hh  = t >> 7;
    int ccp = t & 63,  hh4 = t >> 6;
    int wm = warp & 1, wn = warp >> 1;
    int m0 = wm * 80, o0w = wn * 32;
    int a_row = m0 + (lane & 15), a_col = (lane >> 4) * 8;
    int b_row = o0w + (lane & 7) + ((lane >> 4) ? 8 : 0);
    int b_col = ((lane >> 3) & 1) * 8;
    uint32_t uGh = smem_u32(gh), uGl = smem_u32(gl);
    uint32_t uWh = smem_u32(wh), uWl = smem_u32(wl);

    for (int grp = blockIdx.x; grp < NP/8; grp += gridDim.x) {
        int pt0 = grp * 8;
        int b = pt0 / NN;
        __syncthreads();
        for (int i = t; i < 1024; i += 256) c1s[i] = C1[(size_t)pt0*128 + i];
        if (t < 160) { int p = t / 20, k = t - p*20; ixs[t] = idx[(size_t)(pt0+p)*KK + k]; }
        __syncthreads();

#pragma unroll
        for (int p = 0; p < 8; p++) {
            float2 cv = *(const float2*)&c1s[p*128 + ccp*2];
            float mx = -3.4e38f, my = -3.4e38f;
#pragma unroll
            for (int k = 0; k < 5; k++) {
                int pk = p*20 + hh4 + 4*k;
                float2 a = *(const float2*)&A1[((size_t)(b*NN + ixs[pk]))*128 + ccp*2];
                float g0 = fmaxf(a.x + cv.x, 0.f);
                float g1 = fmaxf(a.y + cv.y, 0.f);
                __nv_bfloat16 h0, l0, h1, l1;
                bf16split(g0, h0, l0); bf16split(g1, h1, l1);
                *(__nv_bfloat162*)&gh[pk*E2_CPAD + ccp*2] = __nv_bfloat162(h0, h1);
                *(__nv_bfloat162*)&gl[pk*E2_CPAD + ccp*2] = __nv_bfloat162(l0, l1);
                mx = fmaxf(mx, g0); my = fmaxf(my, g1);
            }
            float2 pm; pm.x = mx; pm.y = my;
            *(float2*)&px1[(hh4*8 + p)*128 + ccp*2] = pm;
        }
        __syncthreads();

#pragma unroll
        for (int pi = 0; pi < 4; pi++) {
            int p = hh*4 + pi;
            float x1 = fmaxf(fmaxf(px1[p*128 + cc], px1[1024 + p*128 + cc]),
                             fmaxf(px1[2048 + p*128 + cc], px1[3072 + p*128 + cc]));
            size_t ci = (size_t)(pt0+p)*512 + cc;
            __nv_bfloat16 h, l; bf16split(x1, h, l);
            cath[ci] = h; catl[ci] = l;
        }

        float acc[5][4][4];
#pragma unroll
        for (int mi = 0; mi < 5; mi++)
#pragma unroll
            for (int ni = 0; ni < 4; ni++)
#pragma unroll
                for (int e = 0; e < 4; e++) acc[mi][ni][e] = 0.f;
#pragma unroll
        for (int ks = 0; ks < 8; ks++) {
            int k0 = ks * 16;
            uint32_t ah[5][4], al[5][4];
#pragma unroll
            for (int mi = 0; mi < 5; mi++) {
                uint32_t off = (uint32_t)(((a_row + mi*16)*E2_CPAD + a_col + k0) * 2);
                ldmx4(ah[mi], uGh + off);
                ldmx4(al[mi], uGl + off);
            }
            uint32_t bh[2][4], bl[2][4];
#pragma unroll
            for (int j = 0; j < 2; j++) {
                uint32_t off = (uint32_t)(((b_row + j*16)*E2_CPAD + b_col + k0) * 2);
                ldmx4(bh[j], uWh + off);
                ldmx4(bl[j], uWl + off);
            }
#pragma unroll
            for (int mi = 0; mi < 5; mi++)
#pragma unroll
                for (int j = 0; j < 2; j++)
#pragma unroll
                    for (int sub = 0; sub < 2; sub++) {
                        int ni = j*2 + sub;
                        mma16816(acc[mi][ni], ah[mi], bh[j] + sub*2);
                        mma16816(acc[mi][ni], ah[mi], bl[j] + sub*2);
                        mma16816(acc[mi][ni], al[mi], bh[j] + sub*2);
                    }
        }
        __syncthreads();

        int r = lane >> 2, c2 = (lane & 3) * 2;
#pragma unroll
        for (int mi = 0; mi < 5; mi++)
#pragma unroll
            for (int ni = 0; ni < 4; ni++) {
                int row = m0 + mi*16 + r;
                int o = o0w + ni*8 + c2;
                stage[row*E2_SPAD + o]       = acc[mi][ni][0];
                stage[row*E2_SPAD + o + 1]   = acc[mi][ni][1];
                stage[(row+8)*E2_SPAD + o]   = acc[mi][ni][2];
                stage[(row+8)*E2_SPAD + o+1] = acc[mi][ni][3];
            }
        __syncthreads();

#pragma unroll
        for (int pi = 0; pi < 4; pi++) {
            int p = hh*4 + pi;
            float m = -3.4e38f;
#pragma unroll 4
            for (int k = 0; k < 20; k++) m = fmaxf(m, stage[(p*20 + k)*E2_SPAD + cc]);
            float x2 = fmaxf(m + b2s[cc], 0.f);
            size_t ci = (size_t)(pt0+p)*512 + 128 + cc;
            __nv_bfloat16 h, l; bf16split(x2, h, l);
            cath[ci] = h; catl[ci] = l;
        }
    }
}

// ---------------- precomp A3/C3 via mma.sync 3-term ------------------------------
#define FG_PAD 72
#define FG_SMEM (4*128*FG_PAD*2)

__global__ __launch_bounds__(256) void precomp_mma_kernel(
    const __nv_bfloat16* __restrict__ catH, const __nv_bfloat16* __restrict__ catL,
    const __nv_bfloat16* __restrict__ wH,   const __nv_bfloat16* __restrict__ wL,
    const float* __restrict__ bias, float* __restrict__ A3, float* __restrict__ C3)
{
    extern __shared__ char psm[];
    __nv_bfloat16* Ah = (__nv_bfloat16*)psm;
    __nv_bfloat16* Al = Ah + 128*FG_PAD;
    __nv_bfloat16* Bh = Al + 128*FG_PAD;
    __nv_bfloat16* Bl = Bh + 128*FG_PAD;
    __shared__ float bs[128];
    int t = threadIdx.x, lane = t & 31, warp = t >> 5;
    int wm = warp & 3, wn = warp >> 2;
    int pt0 = blockIdx.x * 128;
    int o0  = blockIdx.y * 128;
    bool isC = (o0 >= 256);
    if (t < 128) bs[t] = isC ? bias[o0 - 256 + t] : 0.f;

    float acc[2][8][4];
#pragma unroll
    for (int mi = 0; mi < 2; mi++)
#pragma unroll
        for (int ni = 0; ni < 8; ni++)
#pragma unroll
            for (int e = 0; e < 4; e++) acc[mi][ni][e] = 0.f;

    int a_row = wm*32 + (lane & 15);
    int a_col = (lane >> 4) * 8;
    int b_row = wn*64 + (lane & 7) + ((lane >> 4) ? 8 : 0);
    int b_col = ((lane >> 3) & 1) * 8;
    uint32_t uAh = smem_u32(Ah), uAl = smem_u32(Al);
    uint32_t uBh = smem_u32(Bh), uBl = smem_u32(Bl);

    for (int kc = 0; kc < 2; kc++) {
        __syncthreads();
        for (int i = t; i < 1024; i += 256) {
            int r = i >> 3, c = (i & 7) * 8;
            size_t gA = (size_t)(pt0 + r)*512 + 128 + kc*64 + c;
            size_t gB = (size_t)(o0 + r)*128 + kc*64 + c;
            *(uint4*)&Ah[r*FG_PAD + c] = *(const uint4*)&catH[gA];
            *(uint4*)&Al[r*FG_PAD + c] = *(const uint4*)&catL[gA];
            *(uint4*)&Bh[r*FG_PAD + c] = *(const uint4*)&wH[gB];
            *(uint4*)&Bl[r*FG_PAD + c] = *(const uint4*)&wL[gB];
        }
        __syncthreads();
#pragma unroll
        for (int ks = 0; ks < 4; ks++) {
            int k0 = ks * 16;
            uint32_t ah[2][4], al[2][4];
#pragma unroll
            for (int mi = 0; mi < 2; mi++) {
                uint32_t off = (uint32_t)(((a_row + mi*16)*FG_PAD + a_col + k0) * 2);
                ldmx4(ah[mi], uAh + off);
                ldmx4(al[mi], uAl + off);
            }
#pragma unroll
            for (int j = 0; j < 4; j++) {
                uint32_t bh[4], bl[4];
                uint32_t off = (uint32_t)(((b_row + j*16)*FG_PAD + b_col + k0) * 2);
                ldmx4(bh, uBh + off);
                ldmx4(bl, uBl + off);
#pragma unroll
                for (int sub = 0; sub < 2; sub++) {
                    int ni = j*2 + sub;
#pragma unroll
                    for (int mi = 0; mi < 2; mi++) {
                        mma16816(acc[mi][ni], ah[mi], bh + sub*2);
                        mma16816(acc[mi][ni], ah[mi], bl + sub*2);
                        mma16816(acc[mi][ni], al[mi], bh + sub*2);
                    }
                }
            }
        }
    }

    __syncthreads();
    float* stage = (float*)psm;      // [128m][132o]
    int r = lane >> 2, c = (lane & 3) * 2;
#pragma unroll
    for (int mi = 0; mi < 2; mi++) {
#pragma unroll
        for (int ni = 0; ni < 8; ni++) {
            int m = wm*32 + mi*16 + r;
            int o = wn*64 + ni*8 + c;
            stage[(m  )*132 + o    ] = acc[mi][ni][0];
            stage[(m  )*132 + o + 1] = acc[mi][ni][1];
            stage[(m+8)*132 + o    ] = acc[mi][ni][2];
            stage[(m+8)*132 + o + 1] = acc[mi][ni][3];
        }
    }
    __syncthreads();
    float* dst = isC ? C3 : A3;
    int ob = o0 & 255;
    for (int i = t; i < 128*128; i += 256) {
        int m = i >> 7, o = i & 127;
        dst[(size_t)(pt0 + m)*256 + ob + o] = stage[m*132 + o] + bs[o];
    }
}

// ---------------- edge-conv3 -----------------------------------------------------
__global__ __launch_bounds__(256) void edge3_kernel(
    const float* __restrict__ A3, const float* __restrict__ C3,
    const int* __restrict__ idx,
    __nv_bfloat16* __restrict__ cath, __nv_bfloat16* __restrict__ catl)
{
    __shared__ float2 c3s[2][128];
    __shared__ int ixs[2][KK];
    int t = threadIdx.x;
    int cc = t & 127, hh = t >> 7;
    for (int grp = blockIdx.x; grp < NP/2; grp += gridDim.x) {
        int pt = grp*2 + hh;
        __syncthreads();
        c3s[hh][cc] = *(const float2*)&C3[(size_t)pt*256 + cc*2];
        if (cc < KK) ixs[hh][cc] = idx[(size_t)pt*KK + cc];
        __syncthreads();
        int b = pt / NN;
        float2 ctr = c3s[hh][cc];
        float m0 = -3.4e38f, m1 = -3.4e38f;
#pragma unroll 4
        for (int k = 0; k < KK; k++) {
            float2 a = *(const float2*)&A3[((size_t)(b*NN + ixs[hh][k]))*256 + cc*2];
            m0 = fmaxf(m0, a.x + ctr.x);
            m1 = fmaxf(m1, a.y + ctr.y);
        }
        m0 = fmaxf(m0, 0.f); m1 = fmaxf(m1, 0.f);
        size_t ci = (size_t)pt*512 + 256 + cc*2;
        __nv_bfloat16 h, l;
        bf16split(m0, h, l); cath[ci] = h;     catl[ci] = l;
        bf16split(m1, h, l); cath[ci + 1] = h; catl[ci + 1] = l;
    }
}

// ---------------- final GEMM via mma.sync bf16 hi/lo 3-term ----------------------
__global__ __launch_bounds__(256) void fgemm_mma_kernel(
    const __nv_bfloat16* __restrict__ catH, const __nv_bfloat16* __restrict__ catL,
    const __nv_bfloat16* __restrict__ w3H,  const __nv_bfloat16* __restrict__ w3L,
    const float* __restrict__ b3, float* __restrict__ out)
{
    extern __shared__ char fsm[];
    __nv_bfloat16* Ah = (__nv_bfloat16*)fsm;
    __nv_bfloat16* Al = Ah + 128*FG_PAD;
    __nv_bfloat16* Bh = Al + 128*FG_PAD;
    __nv_bfloat16* Bl = Bh + 128*FG_PAD;
    __shared__ float b3s[128];
    int t = threadIdx.x, lane = t & 31, warp = t >> 5;
    int wm = warp & 3, wn = warp >> 2;
    int n0 = blockIdx.x * 128;
    int o0 = blockIdx.y * 128;
    if (t < 128) b3s[t] = b3[o0 + t];

    float acc[2][8][4];
#pragma unroll
    for (int mi = 0; mi < 2; mi++)
#pragma unroll
        for (int ni = 0; ni < 8; ni++)
#pragma unroll
            for (int e = 0; e < 4; e++) acc[mi][ni][e] = 0.f;

    int a_row = wm*32 + (lane & 15);
    int a_col = (lane >> 4) * 8;
    int b_row = wn*64 + (lane & 7) + ((lane >> 4) ? 8 : 0);
    int b_col = ((lane >> 3) & 1) * 8;
    uint32_t uAh = smem_u32(Ah), uAl = smem_u32(Al);
    uint32_t uBh = smem_u32(Bh), uBl = smem_u32(Bl);

    for (int kc = 0; kc < 8; kc++) {
        __syncthreads();
        for (int i = t; i < 1024; i += 256) {
            int r = i >> 3, c = (i & 7) * 8;
            size_t gA = (size_t)(n0 + r)*512 + kc*64 + c;
            size_t gB = (size_t)(o0 + r)*512 + kc*64 + c;
            *(uint4*)&Ah[r*FG_PAD + c] = *(const uint4*)&catH[gA];
            *(uint4*)&Al[r*FG_PAD + c] = *(const uint4*)&catL[gA];
            *(uint4*)&Bh[r*FG_PAD + c] = *(const uint4*)&w3H[gB];
            *(uint4*)&Bl[r*FG_PAD + c] = *(const uint4*)&w3L[gB];
        }
        __syncthreads();
#pragma unroll
        for (int ks = 0; ks < 4; ks++) {
            int k0 = ks * 16;
            uint32_t ah[2][4], al[2][4];
#pragma unroll
            for (int mi = 0; mi < 2; mi++) {
                uint32_t off = (uint32_t)(((a_row + mi*16)*FG_PAD + a_col + k0) * 2);
                ldmx4(ah[mi], uAh + off);
                ldmx4(al[mi], uAl + off);
            }
#pragma unroll
            for (int j = 0; j < 4; j++) {
                uint32_t bh[4], bl[4];
                uint32_t off = (uint32_t)(((b_row + j*16)*FG_PAD + b_col + k0) * 2);
                ldmx4(bh, uBh + off);
                ldmx4(bl, uBl + off);
#pragma unroll
                for (int sub = 0; sub < 2; sub++) {
                    int ni = j*2 + sub;
#pragma unroll
                    for (int mi = 0; mi < 2; mi++) {
                        mma16816(acc[mi][ni], ah[mi], bh + sub*2);
                        mma16816(acc[mi][ni], ah[mi], bl + sub*2);
                        mma16816(acc[mi][ni], al[mi], bh + sub*2);
                    }
                }
            }
        }
    }

    __syncthreads();
    float* stage = (float*)fsm;      // [128o][132p]
    int r = lane >> 2, c = (lane & 3) * 2;
#pragma unroll
    for (int mi = 0; mi < 2; mi++) {
#pragma unroll
        for (int ni = 0; ni < 8; ni++) {
            int m = wm*32 + mi*16 + r;
            int o = wn*64 + ni*8 + c;
            stage[(o  )*132 + m    ] = acc[mi][ni][0];
            stage[(o+1)*132 + m    ] = acc[mi][ni][1];
            stage[(o  )*132 + m + 8] = acc[mi][ni][2];
            stage[(o+1)*132 + m + 8] = acc[mi][ni][3];
        }
    }
    __syncthreads();
    int b = n0 >> 12, nn = n0 & 4095;
    for (int i = t; i < 128*128; i += 256) {
        int o = i >> 7, p = i & 127;
        float v = stage[o*132 + p] + b3s[o];
        out[((size_t)(b*1024 + o0 + o))*NN + nn + p] = fmaxf(v, 0.f);
    }
}

// ---------------------------------------------------------------------------------
extern "C" void kernel_launch(void* const* d_in, const int* in_sizes, int n_in,
                              void* d_out, int out_size)
{
    const float* x    = (const float*)d_in[0];
    const float* w1   = (const float*)d_in[1];
    const float* b1   = (const float*)d_in[2];
    const float* w2   = (const float*)d_in[3];
    const float* b2   = (const float*)d_in[4];
    const float* wdg1 = (const float*)d_in[5];
    const float* bdg1 = (const float*)d_in[6];
    const float* wdg2 = (const float*)d_in[7];
    const float* bdg2 = (const float*)d_in[8];
    const float* wsn1 = (const float*)d_in[9];
    const float* bsn1 = (const float*)d_in[10];
    const float* w3   = (const float*)d_in[11];
    const float* b3   = (const float*)d_in[12];
    float* out = (float*)d_out;

    cudaFuncSetAttribute((const void*)phase2_kernel,      cudaFuncAttributeMaxDynamicSharedMemorySize, KM_SMEM);
    cudaFuncSetAttribute((const void*)edge2_kernel,       cudaFuncAttributeMaxDynamicSharedMemorySize, E2_SMEM);
    cudaFuncSetAttribute((const void*)precomp_mma_kernel, cudaFuncAttributeMaxDynamicSharedMemorySize, FG_SMEM);
    cudaFuncSetAttribute((const void*)fgemm_mma_kernel,   cudaFuncAttributeMaxDynamicSharedMemorySize, FG_SMEM);

    void *p_A1, *p_C1, *p_A3, *p_C3, *p_idx1, *p_idx2;
    void *p_cath, *p_catl, *p_w3h, *p_w3l, *p_wsnh, *p_wsnl;
    cudaGetSymbolAddress(&p_A1,   d_A1);
    cudaGetSymbolAddress(&p_C1,   d_C1);
    cudaGetSymbolAddress(&p_A3,   d_A3);
    cudaGetSymbolAddress(&p_C3,   d_C3);
    cudaGetSymbolAddress(&p_idx1, d_idx1);
    cudaGetSymbolAddress(&p_idx2, d_idx2);
    cudaGetSymbolAddress(&p_cath, d_cath);
    cudaGetSymbolAddress(&p_catl, d_catl);
    cudaGetSymbolAddress(&p_w3h,  d_w3h);
    cudaGetSymbolAddress(&p_w3l,  d_w3l);
    cudaGetSymbolAddress(&p_wsnh, d_wsnh);
    cudaGetSymbolAddress(&p_wsnl, d_wsnl);

    // phase 1: mlp || w3 split || wsn split
    phase1_kernel<<<768, 256>>>(x, w1, b1, w2, b2, w3, wsn1);

    // phase 2: precomp64 || knn64 || knn3 (interleaved block types)
    phase2_kernel<<<1172, 256, KM_SMEM>>>(x, wdg1, bdg1);

    edge2_kernel<<<148, 256, E2_SMEM>>>(
        (const float*)p_A1, (const float*)p_C1, (const int*)p_idx1, wdg2, bdg2,
        (__nv_bfloat16*)p_cath, (__nv_bfloat16*)p_catl);

    precomp_mma_kernel<<<dim3(NP/128, 4), 256, FG_SMEM>>>(
        (const __nv_bfloat16*)p_cath, (const __nv_bfloat16*)p_catl,
        (const __nv_bfloat16*)p_wsnh, (const __nv_bfloat16*)p_wsnl,
        bsn1, (float*)p_A3, (float*)p_C3);

    edge3_kernel<<<512, 256>>>((const float*)p_A3, (const float*)p_C3, (const int*)p_idx2,
        (__nv_bfloat16*)p_cath, (__nv_bfloat16*)p_catl);

    fgemm_mma_kernel<<<dim3(NP/128, 8), 256, FG_SMEM>>>(
        (const __nv_bfloat16*)p_cath, (const __nv_bfloat16*)p_catl,
        (const __nv_bfloat16*)p_w3h,  (const __nv_bfloat16*)p_w3l, b3, out);
}

// round 15
// speedup vs baseline: 1.5631x; 1.5631x over previous
#include <cuda_runtime.h>
#include <cuda_bf16.h>
#include <cstdint>

#define BB 8
#define NN 4096
#define NP (BB*NN)
#define KK 20

typedef unsigned long long ull;
typedef unsigned short ushort_t;

__device__ __forceinline__ ull pk2(float a, float b){ ull r; asm("mov.b64 %0, {%1,%2};" : "=l"(r) : "f"(a), "f"(b)); return r; }
__device__ __forceinline__ ull fma2(ull a, ull b, ull c){ ull d; asm("fma.rn.f32x2 %0, %1, %2, %3;" : "=l"(d) : "l"(a), "l"(b), "l"(c)); return d; }
__device__ __forceinline__ void upk(ull v, float& a, float& b){ asm("mov.b64 {%0,%1}, %2;" : "=f"(a), "=f"(b) : "l"(v)); }

__device__ __forceinline__ uint32_t smem_u32(const void* p) {
    uint32_t a;
    asm("{ .reg .u64 tmp; cvta.to.shared.u64 tmp, %1; cvt.u32.u64 %0, tmp; }" : "=r"(a) : "l"(p));
    return a;
}
__device__ __forceinline__ void ldmx4(uint32_t* r, uint32_t addr) {
    asm volatile("ldmatrix.sync.aligned.m8n8.x4.shared.b16 {%0,%1,%2,%3}, [%4];"
        : "=r"(r[0]), "=r"(r[1]), "=r"(r[2]), "=r"(r[3]) : "r"(addr));
}
__device__ __forceinline__ void mma16816(float* d, const uint32_t* a, const uint32_t* b) {
    asm volatile("mma.sync.aligned.m16n8k16.row.col.f32.bf16.bf16.f32 "
        "{%0,%1,%2,%3}, {%4,%5,%6,%7}, {%8,%9}, {%0,%1,%2,%3};"
        : "+f"(d[0]), "+f"(d[1]), "+f"(d[2]), "+f"(d[3])
        : "r"(a[0]), "r"(a[1]), "r"(a[2]), "r"(a[3]), "r"(b[0]), "r"(b[1]));
}
__device__ __forceinline__ void bf16split(float v, __nv_bfloat16& h, __nv_bfloat16& l) {
    h = __float2bfloat16_rn(v);
    l = __float2bfloat16_rn(v - __bfloat162float(h));
}

// ---------------- scratch -------------------------------------------------------
__device__ float d_h[NP*64];
__device__ __nv_bfloat16 d_hh[NP*64];
__device__ __nv_bfloat16 d_hl[NP*64];
__device__ float d_hsq[NP];
__device__ float d_xsq[NP];
__device__ int   d_idx1[NP*KK];
__device__ int   d_idx2[NP*KK];
__device__ float d_A1[NP*128];
__device__ float d_C1[NP*128];
__device__ float d_A3[(size_t)NP*256];
__device__ float d_C3[(size_t)NP*256];
__device__ __nv_bfloat16 d_cath[(size_t)NP*512];
__device__ __nv_bfloat16 d_catl[(size_t)NP*512];
__device__ __nv_bfloat16 d_w3h[1024*512];
__device__ __nv_bfloat16 d_w3l[1024*512];
__device__ __nv_bfloat16 d_wsnh[512*128];
__device__ __nv_bfloat16 d_wsnl[512*128];

// ================= phase 1 bodies ===============================================
__device__ void mlp_body(int blk,
    const float* __restrict__ x, const float* __restrict__ w1, const float* __restrict__ b1,
    const float* __restrict__ w2, const float* __restrict__ b2)
{
    __shared__ float w1s[192], b1s[64], b2s[64], w2s[4096];
    int t = threadIdx.x;
    for (int i = t; i < 192; i += 256) w1s[i] = w1[i];
    if (t < 64) { b1s[t] = b1[t]; b2s[t] = b2[t]; }
    for (int i = t; i < 4096; i += 256) w2s[i] = w2[i];
    __syncthreads();
    int pt = blk * 256 + t;
    float x0 = x[pt*3+0], x1 = x[pt*3+1], x2 = x[pt*3+2];
    d_xsq[pt] = x0*x0 + x1*x1 + x2*x2;
    float h1[64];
#pragma unroll
    for (int o = 0; o < 64; o++) {
        float a = b1s[o] + w1s[o*3]*x0 + w1s[o*3+1]*x1 + w1s[o*3+2]*x2;
        h1[o] = fmaxf(a, 0.f);
    }
    float sq = 0.f;
#pragma unroll 2
    for (int o = 0; o < 64; o++) {
        float a = b2s[o];
#pragma unroll
        for (int c = 0; c < 64; c++) a += w2s[o*64+c] * h1[c];
        a = fmaxf(a, 0.f);
        d_h[(size_t)pt*64 + o] = a;
        __nv_bfloat16 h, l; bf16split(a, h, l);
        d_hh[(size_t)pt*64 + o] = h;
        d_hl[(size_t)pt*64 + o] = l;
        sq += a*a;
    }
    d_hsq[pt] = sq;
}

__device__ void cvt_split_body(int blk, const float* __restrict__ src,
    __nv_bfloat16* __restrict__ hi, __nv_bfloat16* __restrict__ lo)
{
    int i = (blk * 256 + threadIdx.x) * 4;
    float4 v = *(const float4*)&src[i];
    __nv_bfloat16 h0, h1, h2, h3, l0, l1, l2, l3;
    bf16split(v.x, h0, l0); bf16split(v.y, h1, l1);
    bf16split(v.z, h2, l2); bf16split(v.w, h3, l3);
    __nv_bfloat162* hp = (__nv_bfloat162*)&hi[i];
    __nv_bfloat162* lp = (__nv_bfloat162*)&lo[i];
    hp[0] = __nv_bfloat162(h0, h1); hp[1] = __nv_bfloat162(h2, h3);
    lp[0] = __nv_bfloat162(l0, l1); lp[1] = __nv_bfloat162(l2, l3);
}

__device__ void wsn_split_body(int blk, const float* __restrict__ wsn1,
    __nv_bfloat16* __restrict__ wh, __nv_bfloat16* __restrict__ wl)
{
    int i = blk * 256 + threadIdx.x;
    int o = i >> 7, c = i & 127;
    float va = wsn1[o*256 + c];
    float vb = wsn1[o*256 + 128 + c];
    __nv_bfloat16 h, l;
    bf16split(va, h, l);
    wh[o*128 + c] = h; wl[o*128 + c] = l;
    bf16split(vb - va, h, l);
    wh[(256 + o)*128 + c] = h; wl[(256 + o)*128 + c] = l;
}

__global__ __launch_bounds__(256) void phase1_kernel(
    const float* __restrict__ x, const float* __restrict__ w1, const float* __restrict__ b1,
    const float* __restrict__ w2, const float* __restrict__ b2,
    const float* __restrict__ w3, const float* __restrict__ wsn1)
{
    int blk = blockIdx.x;
    if (blk < 128)      mlp_body(blk, x, w1, b1, w2, b2);
    else if (blk < 640) cvt_split_body(blk - 128, w3, d_w3h, d_w3l);
    else                wsn_split_body(blk - 640, wsn1, d_wsnh, d_wsnl);
}

// ================= phase 2 bodies ===============================================
// ---- knn64 via mma (staged ds, gated scan, consolidated rebuild) ----
#define KM_QPAD 72
#define KM_QH 0
#define KM_QL (64*KM_QPAD*2)
#define KM_CH (2*64*KM_QPAD*2)
#define KM_CL (3*64*KM_QPAD*2)
#define KM_QXX (4*64*KM_QPAD*2)
#define KM_CXX (KM_QXX + 256)
#define KM_DS  (KM_CXX + 256)
#define KM_SV  (KM_DS + 64*68*4)
#define KM_BV  (KM_SV + 20*256*4)
#define KM_SI  (KM_BV + 16*256*4)
#define KM_BI  (KM_SI + 20*256*2)
#define KM_SMEM (KM_BI + 16*256*2)

__device__ void knn64_body(char* kms, int blk,
    const __nv_bfloat16* __restrict__ hh, const __nv_bfloat16* __restrict__ hl,
    const float* __restrict__ sq, int* __restrict__ out)
{
    const int QT = 64, CT = 64;
    __nv_bfloat16* qh = (__nv_bfloat16*)(kms + KM_QH);
    __nv_bfloat16* ql = (__nv_bfloat16*)(kms + KM_QL);
    __nv_bfloat16* ch = (__nv_bfloat16*)(kms + KM_CH);
    __nv_bfloat16* cl = (__nv_bfloat16*)(kms + KM_CL);
    float* qxx = (float*)(kms + KM_QXX);
    float* cxx = (float*)(kms + KM_CXX);
    float* ds  = (float*)(kms + KM_DS);
    float* sv  = (float*)(kms + KM_SV);
    float* bv  = (float*)(kms + KM_BV);
    ushort_t* si = (ushort_t*)(kms + KM_SI);
    ushort_t* bi = (ushort_t*)(kms + KM_BI);

    int b  = blk / (NN/QT);
    int q0 = (blk % (NN/QT)) * QT;
    int t = threadIdx.x, lane = t & 31, warp = t >> 5;
    int qq = t >> 2, s = t & 3;
    int wm = warp & 3, wn = warp >> 2;
    int a_row = wm*16 + (lane & 15), a_col = (lane >> 4) * 8;
    int b_row = wn*32 + (lane & 7) + ((lane >> 4) ? 8 : 0);
    int b_col = ((lane >> 3) & 1) * 8;
    uint32_t uQh = smem_u32(qh), uQl = smem_u32(ql);
    uint32_t uCh = smem_u32(ch), uCl = smem_u32(cl);

    for (int i = t; i < 64*8; i += 256) {
        int r = i >> 3, c = (i & 7) * 8;
        size_t gi = (size_t)(b*NN + q0 + r)*64 + c;
        *(uint4*)&qh[r*KM_QPAD + c] = *(const uint4*)&hh[gi];
        *(uint4*)&ql[r*KM_QPAD + c] = *(const uint4*)&hl[gi];
    }
    if (t < QT) qxx[t] = sq[b*NN + q0 + t];

#pragma unroll
    for (int r = 0; r < KK; r++) { sv[r*256 + t] = -3.4e38f; si[r*256 + t] = 0xFFFF; }
    float minv = -3.4e38f; int minp = 0;
    float gthr = -3.4e38f;

    for (int tile = 0; tile < NN/CT; tile++) {
        __syncthreads();
        for (int i = t; i < 64*8; i += 256) {
            int r = i >> 3, c = (i & 7) * 8;
            size_t gi = (size_t)(b*NN + tile*CT + r)*64 + c;
            *(uint4*)&ch[r*KM_QPAD + c] = *(const uint4*)&hh[gi];
            *(uint4*)&cl[r*KM_QPAD + c] = *(const uint4*)&hl[gi];
        }
        if (t < CT) cxx[t] = sq[b*NN + tile*CT + t];
        __syncthreads();

        float acc[4][4];
#pragma unroll
        for (int ni = 0; ni < 4; ni++)
#pragma unroll
            for (int e = 0; e < 4; e++) acc[ni][e] = 0.f;
#pragma unroll
        for (int ks = 0; ks < 4; ks++) {
            int k0 = ks * 16;
            uint32_t ah[4], al[4];
            uint32_t offA = (uint32_t)((a_row*KM_QPAD + a_col + k0) * 2);
            ldmx4(ah, uQh + offA);
            ldmx4(al, uQl + offA);
#pragma unroll
            for (int j = 0; j < 2; j++) {
                uint32_t bh[4], bl[4];
                uint32_t offB = (uint32_t)(((b_row + j*16)*KM_QPAD + b_col + k0) * 2);
                ldmx4(bh, uCh + offB);
                ldmx4(bl, uCl + offB);
#pragma unroll
                for (int sub = 0; sub < 2; sub++) {
                    int ni = j*2 + sub;
                    mma16816(acc[ni], ah, bh + sub*2);
                    mma16816(acc[ni], ah, bl + sub*2);
                    mma16816(acc[ni], al, bh + sub*2);
                }
            }
        }
        {
            int r = lane >> 2, c2 = (lane & 3) * 2;
            int row0 = wm*16 + r, row1 = row0 + 8;
            float qx0 = qxx[row0], qx1 = qxx[row1];
#pragma unroll
            for (int ni = 0; ni < 4; ni++) {
                int col = wn*32 + ni*8 + c2;
                float cx0 = cxx[col], cx1 = cxx[col+1];
                float2 v0, v1;
                v0.x = 2.f*acc[ni][0] - qx0 - cx0; v0.y = 2.f*acc[ni][1] - qx0 - cx1;
                v1.x = 2.f*acc[ni][2] - qx1 - cx0; v1.y = 2.f*acc[ni][3] - qx1 - cx1;
                *(float2*)&ds[row0*68 + col] = v0;
                *(float2*)&ds[row1*68 + col] = v1;
            }
        }
        __syncthreads();

        int cnt = 0;
        const float* row = &ds[qq*68 + s*16];
        int base = tile*CT + s*16;
#pragma unroll
        for (int c4 = 0; c4 < 4; c4++) {
            float4 v = *(const float4*)&row[c4*4];
            float m = fmaxf(fmaxf(v.x, v.y), fmaxf(v.z, v.w));
            if (m > gthr) {
                int id0 = base + c4*4;
                if (v.x > gthr) { bv[cnt*256+t] = v.x; bi[cnt*256+t] = (ushort_t)(id0  ); cnt++; }
                if (v.y > gthr) { bv[cnt*256+t] = v.y; bi[cnt*256+t] = (ushort_t)(id0+1); cnt++; }
                if (v.z > gthr) { bv[cnt*256+t] = v.z; bi[cnt*256+t] = (ushort_t)(id0+2); cnt++; }
                if (v.w > gthr) { bv[cnt*256+t] = v.w; bi[cnt*256+t] = (ushort_t)(id0+3); cnt++; }
            }
        }
        for (int j = 0; __any_sync(0xffffffffu, j < cnt); j++) {
            if (j < cnt) {
                float d = bv[j*256+t];
                if (d > minv) {
                    sv[minp*256+t] = d; si[minp*256+t] = bi[j*256+t];
                    float mv = sv[t]; int mp = 0;
#pragma unroll
                    for (int r = 1; r < KK; r++) {
                        float x = sv[r*256+t];
                        if (x < mv) { mv = x; mp = r; }
                    }
                    minv = mv; minp = mp;
                }
            }
        }
        float m = minv;
        m = fmaxf(m, __shfl_xor_sync(0xffffffffu, m, 1));
        m = fmaxf(m, __shfl_xor_sync(0xffffffffu, m, 2));
        gthr = m;
    }

#pragma unroll 1
    for (int r = 0; r < KK; r++) {
        float bvv = -3.4e38f; int bid = 0x7fffffff; int bslot = 0;
#pragma unroll
        for (int rr = 0; rr < KK; rr++) {
            float x = sv[rr*256+t]; int xi = si[rr*256+t];
            bool better = (x > bvv) || (x == bvv && xi < bid);
            if (better) { bvv = x; bid = xi; bslot = rr; }
        }
        float v = bvv; int id = bid; int sl = s;
#pragma unroll
        for (int off = 1; off <= 2; off <<= 1) {
            float ov = __shfl_xor_sync(0xffffffffu, v, off);
            int  oid = __shfl_xor_sync(0xffffffffu, id, off);
            int  osl = __shfl_xor_sync(0xffffffffu, sl, off);
            if (ov > v || (ov == v && oid < id)) { v = ov; id = oid; sl = osl; }
        }
        if (sl == s) sv[bslot*256+t] = -3.4e38f;
        if (s == 0) out[((size_t)(b*NN + q0 + qq))*KK + r] = id;
    }
}

// ---- knn small-C (f32x2, staged ds, gated scan) ----
template<int C>
__device__ void knn_small_body(float* km, int blk,
    const float* __restrict__ data, const float* __restrict__ sq, int* __restrict__ out)
{
    const int QT = 64, CT = 64;
    const int QDUP_F = (C*130 + 3) & ~3;
    ull*   qdup = (ull*)km;
    float* csT  = km + QDUP_F;
    float* ds   = csT + C*68;
    float* qxx  = ds + 64*68;
    float* cxx  = qxx + 64;
    float* sv   = cxx + 64;
    float* bv   = sv + 20*256;
    ushort_t* si = (ushort_t*)(bv + 16*256);
    ushort_t* bi = si + 20*256;

    int b  = blk / (NN/QT);
    int q0 = (blk % (NN/QT)) * QT;
    int t = threadIdx.x;
    int tq = t >> 4, tc = t & 15;
    int qq = t >> 2, s = t & 3;

    for (int i = t; i < QT*C; i += 256) {
        int q = i / C, d = i - q*C;
        float v = data[((size_t)(b*NN + q0 + q))*C + d];
        qdup[d*65 + q] = pk2(v, v);
    }
    if (t < QT) qxx[t] = sq[b*NN + q0 + t];

#pragma unroll
    for (int r = 0; r < KK; r++) { sv[r*256 + t] = -3.4e38f; si[r*256 + t] = 0xFFFF; }
    float minv = -3.4e38f; int minp = 0;
    float gthr = -3.4e38f;

    for (int tile = 0; tile < NN/CT; tile++) {
        __syncthreads();
        for (int i = t; i < CT*C; i += 256) {
            int cth = i / C, d = i - cth*C;
            csT[d*68 + cth] = data[((size_t)(b*NN + tile*CT + cth))*C + d];
        }
        if (t < CT) cxx[t] = sq[b*NN + tile*CT + t];
        __syncthreads();

        ull a00=0,a01=0,a10=0,a11=0,a20=0,a21=0,a30=0,a31=0;
#pragma unroll 8
        for (int k = 0; k < C; k++) {
            ulonglong2 cp = *(const ulonglong2*)&csT[k*68 + tc*4];
            const ull* qd = &qdup[k*65 + tq*4];
            ull q0d = qd[0], q1d = qd[1], q2d = qd[2], q3d = qd[3];
            a00 = fma2(q0d, cp.x, a00); a01 = fma2(q0d, cp.y, a01);
            a10 = fma2(q1d, cp.x, a10); a11 = fma2(q1d, cp.y, a11);
            a20 = fma2(q2d, cp.x, a20); a21 = fma2(q2d, cp.y, a21);
            a30 = fma2(q3d, cp.x, a30); a31 = fma2(q3d, cp.y, a31);
        }
        float cx0 = cxx[tc*4], cx1 = cxx[tc*4+1], cx2 = cxx[tc*4+2], cx3 = cxx[tc*4+3];
        ull accs[4][2] = {{a00,a01},{a10,a11},{a20,a21},{a30,a31}};
#pragma unroll
        for (int i = 0; i < 4; i++) {
            float qx = qxx[tq*4 + i];
            float d0, d1, d2, d3;
            upk(accs[i][0], d0, d1); upk(accs[i][1], d2, d3);
            float4 r;
            r.x = 2.f*d0 - qx - cx0; r.y = 2.f*d1 - qx - cx1;
            r.z = 2.f*d2 - qx - cx2; r.w = 2.f*d3 - qx - cx3;
            *(float4*)&ds[(tq*4 + i)*68 + tc*4] = r;
        }
        __syncthreads();

        int cnt = 0;
        const float* row = &ds[qq*68 + s*16];
        int base = tile*CT + s*16;
#pragma unroll
        for (int c4 = 0; c4 < 4; c4++) {
            float4 v = *(const float4*)&row[c4*4];
            float m = fmaxf(fmaxf(v.x, v.y), fmaxf(v.z, v.w));
            if (m > gthr) {
                int id0 = base + c4*4;
                if (v.x > gthr) { bv[cnt*256+t] = v.x; bi[cnt*256+t] = (ushort_t)(id0  ); cnt++; }
                if (v.y > gthr) { bv[cnt*256+t] = v.y; bi[cnt*256+t] = (ushort_t)(id0+1); cnt++; }
                if (v.z > gthr) { bv[cnt*256+t] = v.z; bi[cnt*256+t] = (ushort_t)(id0+2); cnt++; }
                if (v.w > gthr) { bv[cnt*256+t] = v.w; bi[cnt*256+t] = (ushort_t)(id0+3); cnt++; }
            }
        }
        for (int j = 0; __any_sync(0xffffffffu, j < cnt); j++) {
            if (j < cnt) {
                float d = bv[j*256+t];
                if (d > minv) {
                    sv[minp*256+t] = d; si[minp*256+t] = bi[j*256+t];
                    float mv = sv[t]; int mp = 0;
#pragma unroll
                    for (int r = 1; r < KK; r++) {
                        float x = sv[r*256+t];
                        if (x < mv) { mv = x; mp = r; }
                    }
                    minv = mv; minp = mp;
                }
            }
        }
        float m = minv;
        m = fmaxf(m, __shfl_xor_sync(0xffffffffu, m, 1));
        m = fmaxf(m, __shfl_xor_sync(0xffffffffu, m, 2));
        gthr = m;
    }

#pragma unroll 1
    for (int r = 0; r < KK; r++) {
        float bvv = -3.4e38f; int bid = 0x7fffffff; int bslot = 0;
#pragma unroll
        for (int rr = 0; rr < KK; rr++) {
            float x = sv[rr*256+t]; int xi = si[rr*256+t];
            bool better = (x > bvv) || (x == bvv && xi < bid);
            if (better) { bvv = x; bid = xi; bslot = rr; }
        }
        float v = bvv; int id = bid; int sl = s;
#pragma unroll
        for (int off = 1; off <= 2; off <<= 1) {
            float ov = __shfl_xor_sync(0xffffffffu, v, off);
            int  oid = __shfl_xor_sync(0xffffffffu, id, off);
            int  osl = __shfl_xor_sync(0xffffffffu, sl, off);
            if (ov > v || (ov == v && oid < id)) { v = ov; id = oid; sl = osl; }
        }
        if (sl == s) sv[bslot*256+t] = -3.4e38f;
        if (s == 0) out[((size_t)(b*NN + q0 + qq))*KK + r] = id;
    }
}

// ---- precomp64 (f32x2) ----
__device__ void precomp64_body(float* sm, int blk, int nblk,
    const float* __restrict__ in,
    const float* __restrict__ W, const float* __restrict__ bias,
    float* __restrict__ A, float* __restrict__ Cc)
{
    const int CIN = 64;
    float* wa = sm;
    float* wd = sm + CIN*128;
    ull* invd = (ull*)(sm + 2*CIN*128);
    int t = threadIdx.x;
    int to = t & 31, rr = (t >> 5) & 1, pp = t >> 6;
    int o4 = 4*to;

    for (int i = t; i < 128*2*CIN; i += 256) {
        int oo = i / (2*CIN), c = i - oo*(2*CIN);
        float v = W[i];
        if (c < CIN) wa[c*128 + oo] = v; else wd[(c-CIN)*128 + oo] = v;
    }
    __syncthreads();
    for (int i = t; i < CIN*128; i += 256) wd[i] -= wa[i];
    ull bb0 = 0, bb1 = 0;
    if (rr) { bb0 = pk2(bias[o4], bias[o4+1]); bb1 = pk2(bias[o4+2], bias[o4+3]); }
    const float* src = rr ? wd : wa;
    float* dst = rr ? Cc : A;
    __syncthreads();

    for (int grp = blk; grp < NP/8; grp += nblk) {
        __syncthreads();
        for (int i = t; i < 8*CIN; i += 256) {
            int c = i & (CIN-1), p = i >> 6;
            float v = in[(size_t)(grp*8 + p)*64 + c];
            invd[c*8 + p] = pk2(v, v);
        }
        __syncthreads();
        ull acc[2][2] = {{bb0, bb1}, {bb0, bb1}};
#pragma unroll 4
        for (int c = 0; c < CIN; c++) {
            ulonglong2 wp = *(const ulonglong2*)&src[c*128 + o4];
            ull iv0 = invd[c*8 + 2*pp], iv1 = invd[c*8 + 2*pp + 1];
            acc[0][0] = fma2(wp.x, iv0, acc[0][0]);
            acc[0][1] = fma2(wp.y, iv0, acc[0][1]);
            acc[1][0] = fma2(wp.x, iv1, acc[1][0]);
            acc[1][1] = fma2(wp.y, iv1, acc[1][1]);
        }
#pragma unroll
        for (int pt = 0; pt < 2; pt++) {
            size_t base = (size_t)(grp*8 + 2*pp + pt)*128 + o4;
            *(ull*)&dst[base]     = acc[pt][0];
            *(ull*)&dst[base + 2] = acc[pt][1];
        }
    }
}

__global__ __launch_bounds__(256, 2) void phase2_kernel(
    const float* __restrict__ x,
    const float* __restrict__ wdg1, const float* __restrict__ bdg1)
{
    extern __shared__ char dsm[];
    int blk = blockIdx.x;
    if (blk < 512)
        knn64_body(dsm, blk, d_hh, d_hl, d_hsq, d_idx1);
    else if (blk < 1024)
        knn_small_body<3>((float*)dsm, blk - 512, x, d_xsq, d_idx2);
    else
        precomp64_body((float*)dsm, blk - 1024, 148, d_h, wdg1, bdg1, d_A1, d_C1);
}

// ---------------- kernel 4: fused edge-conv1 + edge-conv2 via mma.sync -----------
#define E2_CPAD 136
#define E2_SPAD 132
#define E2_WH 0
#define E2_WL (128*E2_CPAD*2)
#define E2_G  (E2_WL + 128*E2_CPAD*2)
#define E2_GL_OFF (160*E2_CPAD*2)
#define E2_C1 (E2_G + 2*160*E2_CPAD*2)
#define E2_PX1 (E2_C1 + 1024*4)
#define E2_B2 (E2_PX1 + 4096*4)
#define E2_IXS (E2_B2 + 512)
#define E2_SMEM (E2_IXS + 640)

__global__ __launch_bounds__(256) void edge2_kernel(
    const float* __restrict__ A1, const float* __restrict__ C1,
    const int* __restrict__ idx, const float* __restrict__ w2,
    const float* __restrict__ b2,
    __nv_bfloat16* __restrict__ cath, __nv_bfloat16* __restrict__ catl)
{
    extern __shared__ char esm[];
    __nv_bfloat16* wh = (__nv_bfloat16*)(esm + E2_WH);
    __nv_bfloat16* wl = (__nv_bfloat16*)(esm + E2_WL);
    __nv_bfloat16* gh = (__nv_bfloat16*)(esm + E2_G);
    __nv_bfloat16* gl = (__nv_bfloat16*)(esm + E2_G + E2_GL_OFF);
    float* stage = (float*)(esm + E2_G);
    float* c1s = (float*)(esm + E2_C1);
    float* px1 = (float*)(esm + E2_PX1);
    float* b2s = (float*)(esm + E2_B2);
    int*   ixs = (int*)(esm + E2_IXS);

    int t = threadIdx.x, lane = t & 31, warp = t >> 5;
    for (int i = t; i < 128*128; i += 256) {
        float v = w2[i];
        __nv_bfloat16 h, l; bf16split(v, h, l);
        int o = i >> 7, c = i & 127;
        wh[o*E2_CPAD + c] = h; wl[o*E2_CPAD + c] = l;
    }
    if (t < 128) b2s[t] = b2[t];
    __syncthreads();

    int cc  = t & 127, hh  = t >> 7;
    int ccp = t & 63,  hh4 = t >> 6;
    int wm = warp & 1, wn = warp >> 1;
    int m0 = wm * 80, o0w = wn * 32;
    int a_row = m0 + (lane & 15), a_col = (lane >> 4) * 8;
    int b_row = o0w + (lane & 7) + ((lane >> 4) ? 8 : 0);
    int b_col = ((lane >> 3) & 1) * 8;
    uint32_t uGh = smem_u32(gh), uGl = smem_u32(gl);
    uint32_t uWh = smem_u32(wh), uWl = smem_u32(wl);

    for (int grp = blockIdx.x; grp < NP/8; grp += gridDim.x) {
        int pt0 = grp * 8;
        int b = pt0 / NN;
        __syncthreads();
        for (int i = t; i < 1024; i += 256) c1s[i] = C1[(size_t)pt0*128 + i];
        if (t < 160) { int p = t / 20, k = t - p*20; ixs[t] = idx[(size_t)(pt0+p)*KK + k]; }
        __syncthreads();

#pragma unroll
        for (int p = 0; p < 8; p++) {
            float2 cv = *(const float2*)&c1s[p*128 + ccp*2];
            float mx = -3.4e38f, my = -3.4e38f;
#pragma unroll
            for (int k = 0; k < 5; k++) {
                int pk = p*20 + hh4 + 4*k;
                float2 a = *(const float2*)&A1[((size_t)(b*NN + ixs[pk]))*128 + ccp*2];
                float g0 = fmaxf(a.x + cv.x, 0.f);
                float g1 = fmaxf(a.y + cv.y, 0.f);
                __nv_bfloat16 h0, l0, h1, l1;
                bf16split(g0, h0, l0); bf16split(g1, h1, l1);
                *(__nv_bfloat162*)&gh[pk*E2_CPAD + ccp*2] = __nv_bfloat162(h0, h1);
                *(__nv_bfloat162*)&gl[pk*E2_CPAD + ccp*2] = __nv_bfloat162(l0, l1);
                mx = fmaxf(mx, g0); my = fmaxf(my, g1);
            }
            float2 pm; pm.x = mx; pm.y = my;
            *(float2*)&px1[(hh4*8 + p)*128 + ccp*2] = pm;
        }
        __syncthreads();

#pragma unroll
        for (int pi = 0; pi < 4; pi++) {
            int p = hh*4 + pi;
            float x1 = fmaxf(fmaxf(px1[p*128 + cc], px1[1024 + p*128 + cc]),
                             fmaxf(px1[2048 + p*128 + cc], px1[3072 + p*128 + cc]));
            size_t ci = (size_t)(pt0+p)*512 + cc;
            __nv_bfloat16 h, l; bf16split(x1, h, l);
            cath[ci] = h; catl[ci] = l;
        }

        float acc[5][4][4];
#pragma unroll
        for (int mi = 0; mi < 5; mi++)
#pragma unroll
            for (int ni = 0; ni < 4; ni++)
#pragma unroll
                for (int e = 0; e < 4; e++) acc[mi][ni][e] = 0.f;
#pragma unroll
        for (int ks = 0; ks < 8; ks++) {
            int k0 = ks * 16;
            uint32_t ah[5][4], al[5][4];
#pragma unroll
            for (int mi = 0; mi < 5; mi++) {
                uint32_t off = (uint32_t)(((a_row + mi*16)*E2_CPAD + a_col + k0) * 2);
                ldmx4(ah[mi], uGh + off);
                ldmx4(al[mi], uGl + off);
            }
            uint32_t bh[2][4], bl[2][4];
#pragma unroll
            for (int j = 0; j < 2; j++) {
                uint32_t off = (uint32_t)(((b_row + j*16)*E2_CPAD + b_col + k0) * 2);
                ldmx4(bh[j], uWh + off);
                ldmx4(bl[j], uWl + off);
            }
#pragma unroll
            for (int mi = 0; mi < 5; mi++)
#pragma unroll
                for (int j = 0; j < 2; j++)
#pragma unroll
                    for (int sub = 0; sub < 2; sub++) {
                        int ni = j*2 + sub;
                        mma16816(acc[mi][ni], ah[mi], bh[j] + sub*2);
                        mma16816(acc[mi][ni], ah[mi], bl[j] + sub*2);
                        mma16816(acc[mi][ni], al[mi], bh[j] + sub*2);
                    }
        }
        __syncthreads();

        int r = lane >> 2, c2 = (lane & 3) * 2;
#pragma unroll
        for (int mi = 0; mi < 5; mi++)
#pragma unroll
            for (int ni = 0; ni < 4; ni++) {
                int row = m0 + mi*16 + r;
                int o = o0w + ni*8 + c2;
                stage[row*E2_SPAD + o]       = acc[mi][ni][0];
                stage[row*E2_SPAD + o + 1]   = acc[mi][ni][1];
                stage[(row+8)*E2_SPAD + o]   = acc[mi][ni][2];
                stage[(row+8)*E2_SPAD + o+1] = acc[mi][ni][3];
            }
        __syncthreads();

#pragma unroll
        for (int pi = 0; pi < 4; pi++) {
            int p = hh*4 + pi;
            float m = -3.4e38f;
#pragma unroll 4
            for (int k = 0; k < 20; k++) m = fmaxf(m, stage[(p*20 + k)*E2_SPAD + cc]);
            float x2 = fmaxf(m + b2s[cc], 0.f);
            size_t ci = (size_t)(pt0+p)*512 + 128 + cc;
            __nv_bfloat16 h, l; bf16split(x2, h, l);
            cath[ci] = h; catl[ci] = l;
        }
    }
}

// ---------------- precomp A3/C3 via mma.sync 3-term ------------------------------
#define FG_PAD 72
#define FG_SMEM (4*128*FG_PAD*2)

__global__ __launch_bounds__(256) void precomp_mma_kernel(
    const __nv_bfloat16* __restrict__ catH, const __nv_bfloat16* __restrict__ catL,
    const __nv_bfloat16* __restrict__ wH,   const __nv_bfloat16* __restrict__ wL,
    const float* __restrict__ bias, float* __restrict__ A3, float* __restrict__ C3)
{
    extern __shared__ char psm[];
    __nv_bfloat16* Ah = (__nv_bfloat16*)psm;
    __nv_bfloat16* Al = Ah + 128*FG_PAD;
    __nv_bfloat16* Bh = Al + 128*FG_PAD;
    __nv_bfloat16* Bl = Bh + 128*FG_PAD;
    __shared__ float bs[128];
    int t = threadIdx.x, lane = t & 31, warp = t >> 5;
    int wm = warp & 3, wn = warp >> 2;
    int pt0 = blockIdx.x * 128;
    int o0  = blockIdx.y * 128;
    bool isC = (o0 >= 256);
    if (t < 128) bs[t] = isC ? bias[o0 - 256 + t] : 0.f;

    float acc[2][8][4];
#pragma unroll
    for (int mi = 0; mi < 2; mi++)
#pragma unroll
        for (int ni = 0; ni < 8; ni++)
#pragma unroll
            for (int e = 0; e < 4; e++) acc[mi][ni][e] = 0.f;

    int a_row = wm*32 + (lane & 15);
    int a_col = (lane >> 4) * 8;
    int b_row = wn*64 + (lane & 7) + ((lane >> 4) ? 8 : 0);
    int b_col = ((lane >> 3) & 1) * 8;
    uint32_t uAh = smem_u32(Ah), uAl = smem_u32(Al);
    uint32_t uBh = smem_u32(Bh), uBl = smem_u32(Bl);

    for (int kc = 0; kc < 2; kc++) {
        __syncthreads();
        for (int i = t; i < 1024; i += 256) {
            int r = i >> 3, c = (i & 7) * 8;
            size_t gA = (size_t)(pt0 + r)*512 + 128 + kc*64 + c;
            size_t gB = (size_t)(o0 + r)*128 + kc*64 + c;
            *(uint4*)&Ah[r*FG_PAD + c] = *(const uint4*)&catH[gA];
            *(uint4*)&Al[r*FG_PAD + c] = *(const uint4*)&catL[gA];
            *(uint4*)&Bh[r*FG_PAD + c] = *(const uint4*)&wH[gB];
            *(uint4*)&Bl[r*FG_PAD + c] = *(const uint4*)&wL[gB];
        }
        __syncthreads();
#pragma unroll
        for (int ks = 0; ks < 4; ks++) {
            int k0 = ks * 16;
            uint32_t ah[2][4], al[2][4];
#pragma unroll
            for (int mi = 0; mi < 2; mi++) {
                uint32_t off = (uint32_t)(((a_row + mi*16)*FG_PAD + a_col + k0) * 2);
                ldmx4(ah[mi], uAh + off);
                ldmx4(al[mi], uAl + off);
            }
#pragma unroll
            for (int j = 0; j < 4; j++) {
                uint32_t bh[4], bl[4];
                uint32_t off = (uint32_t)(((b_row + j*16)*FG_PAD + b_col + k0) * 2);
                ldmx4(bh, uBh + off);
                ldmx4(bl, uBl + off);
#pragma unroll
                for (int sub = 0; sub < 2; sub++) {
                    int ni = j*2 + sub;
#pragma unroll
                    for (int mi = 0; mi < 2; mi++) {
                        mma16816(acc[mi][ni], ah[mi], bh + sub*2);
                        mma16816(acc[mi][ni], ah[mi], bl + sub*2);
                        mma16816(acc[mi][ni], al[mi], bh + sub*2);
                    }
                }
            }
        }
    }

    __syncthreads();
    float* stage = (float*)psm;      // [128m][132o]
    int r = lane >> 2, c = (lane & 3) * 2;
#pragma unroll
    for (int mi = 0; mi < 2; mi++) {
#pragma unroll
        for (int ni = 0; ni < 8; ni++) {
            int m = wm*32 + mi*16 + r;
            int o = wn*64 + ni*8 + c;
            stage[(m  )*132 + o    ] = acc[mi][ni][0];
            stage[(m  )*132 + o + 1] = acc[mi][ni][1];
            stage[(m+8)*132 + o    ] = acc[mi][ni][2];
            stage[(m+8)*132 + o + 1] = acc[mi][ni][3];
        }
    }
    __syncthreads();
    float* dst = isC ? C3 : A3;
    int ob = o0 & 255;
    for (int i = t; i < 128*128; i += 256) {
        int m = i >> 7, o = i & 127;
        dst[(size_t)(pt0 + m)*256 + ob + o] = stage[m*132 + o] + bs[o];
    }
}

// ---------------- edge-conv3 -----------------------------------------------------
__global__ __launch_bounds__(256) void edge3_kernel(
    const float* __restrict__ A3, const float* __restrict__ C3,
    const int* __restrict__ idx,
    __nv_bfloat16* __restrict__ cath, __nv_bfloat16* __restrict__ catl)
{
    __shared__ float2 c3s[2][128];
    __shared__ int ixs[2][KK];
    int t = threadIdx.x;
    int cc = t & 127, hh = t >> 7;
    for (int grp = blockIdx.x; grp < NP/2; grp += gridDim.x) {
        int pt = grp*2 + hh;
        __syncthreads();
        c3s[hh][cc] = *(const float2*)&C3[(size_t)pt*256 + cc*2];
        if (cc < KK) ixs[hh][cc] = idx[(size_t)pt*KK + cc];
        __syncthreads();
        int b = pt / NN;
        float2 ctr = c3s[hh][cc];
        float m0 = -3.4e38f, m1 = -3.4e38f;
#pragma unroll 4
        for (int k = 0; k < KK; k++) {
            float2 a = *(const float2*)&A3[((size_t)(b*NN + ixs[hh][k]))*256 + cc*2];
            m0 = fmaxf(m0, a.x + ctr.x);
            m1 = fmaxf(m1, a.y + ctr.y);
        }
        m0 = fmaxf(m0, 0.f); m1 = fmaxf(m1, 0.f);
        size_t ci = (size_t)pt*512 + 256 + cc*2;
        __nv_bfloat16 h, l;
        bf16split(m0, h, l); cath[ci] = h;     catl[ci] = l;
        bf16split(m1, h, l); cath[ci + 1] = h; catl[ci + 1] = l;
    }
}

// ---------------- final GEMM via mma.sync bf16 hi/lo 3-term ----------------------
__global__ __launch_bounds__(256) void fgemm_mma_kernel(
    const __nv_bfloat16* __restrict__ catH, const __nv_bfloat16* __restrict__ catL,
    const __nv_bfloat16* __restrict__ w3H,  const __nv_bfloat16* __restrict__ w3L,
    const float* __restrict__ b3, float* __restrict__ out)
{
    extern __shared__ char fsm[];
    __nv_bfloat16* Ah = (__nv_bfloat16*)fsm;
    __nv_bfloat16* Al = Ah + 128*FG_PAD;
    __nv_bfloat16* Bh = Al + 128*FG_PAD;
    __nv_bfloat16* Bl = Bh + 128*FG_PAD;
    __shared__ float b3s[128];
    int t = threadIdx.x, lane = t & 31, warp = t >> 5;
    int wm = warp & 3, wn = warp >> 2;
    int n0 = blockIdx.x * 128;
    int o0 = blockIdx.y * 128;
    if (t < 128) b3s[t] = b3[o0 + t];

    float acc[2][8][4];
#pragma unroll
    for (int mi = 0; mi < 2; mi++)
#pragma unroll
        for (int ni = 0; ni < 8; ni++)
#pragma unroll
            for (int e = 0; e < 4; e++) acc[mi][ni][e] = 0.f;

    int a_row = wm*32 + (lane & 15);
    int a_col = (lane >> 4) * 8;
    int b_row = wn*64 + (lane & 7) + ((lane >> 4) ? 8 : 0);
    int b_col = ((lane >> 3) & 1) * 8;
    uint32_t uAh = smem_u32(Ah), uAl = smem_u32(Al);
    uint32_t uBh = smem_u32(Bh), uBl = smem_u32(Bl);

    for (int kc = 0; kc < 8; kc++) {
        __syncthreads();
        for (int i = t; i < 1024; i += 256) {
            int r = i >> 3, c = (i & 7) * 8;
            size_t gA = (size_t)(n0 + r)*512 + kc*64 + c;
            size_t gB = (size_t)(o0 + r)*512 + kc*64 + c;
            *(uint4*)&Ah[r*FG_PAD + c] = *(const uint4*)&catH[gA];
            *(uint4*)&Al[r*FG_PAD + c] = *(const uint4*)&catL[gA];
            *(uint4*)&Bh[r*FG_PAD + c] = *(const uint4*)&w3H[gB];
            *(uint4*)&Bl[r*FG_PAD + c] = *(const uint4*)&w3L[gB];
        }
        __syncthreads();
#pragma unroll
        for (int ks = 0; ks < 4; ks++) {
            int k0 = ks * 16;
            uint32_t ah[2][4], al[2][4];
#pragma unroll
            for (int mi = 0; mi < 2; mi++) {
                uint32_t off = (uint32_t)(((a_row + mi*16)*FG_PAD + a_col + k0) * 2);
                ldmx4(ah[mi], uAh + off);
                ldmx4(al[mi], uAl + off);
            }
#pragma unroll
            for (int j = 0; j < 4; j++) {
                uint32_t bh[4], bl[4];
                uint32_t off = (uint32_t)(((b_row + j*16)*FG_PAD + b_col + k0) * 2);
                ldmx4(bh, uBh + off);
                ldmx4(bl, uBl + off);
#pragma unroll
                for (int sub = 0; sub < 2; sub++) {
                    int ni = j*2 + sub;
#pragma unroll
                    for (int mi = 0; mi < 2; mi++) {
                        mma16816(acc[mi][ni], ah[mi], bh + sub*2);
                        mma16816(acc[mi][ni], ah[mi], bl + sub*2);
                        mma16816(acc[mi][ni], al[mi], bh + sub*2);
                    }
                }
            }
        }
    }

    __syncthreads();
    float* stage = (float*)fsm;      // [128o][132p]
    int r = lane >> 2, c = (lane & 3) * 2;
#pragma unroll
    for (int mi = 0; mi < 2; mi++) {
#pragma unroll
        for (int ni = 0; ni < 8; ni++) {
            int m = wm*32 + mi*16 + r;
            int o = wn*64 + ni*8 + c;
            stage[(o  )*132 + m    ] = acc[mi][ni][0];
            stage[(o+1)*132 + m    ] = acc[mi][ni][1];
            stage[(o  )*132 + m + 8] = acc[mi][ni][2];
            stage[(o+1)*132 + m + 8] = acc[mi][ni][3];
        }
    }
    __syncthreads();
    int b = n0 >> 12, nn = n0 & 4095;
    for (int i = t; i < 128*128; i += 256) {
        int o = i >> 7, p = i & 127;
        float v = stage[o*132 + p] + b3s[o];
        out[((size_t)(b*1024 + o0 + o))*NN + nn + p] = fmaxf(v, 0.f);
    }
}

// ---------------------------------------------------------------------------------
extern "C" void kernel_launch(void* const* d_in, const int* in_sizes, int n_in,
                              void* d_out, int out_size)
{
    const float* x    = (const float*)d_in[0];
    const float* w1   = (const float*)d_in[1];
    const float* b1   = (const float*)d_in[2];
    const float* w2   = (const float*)d_in[3];
    const float* b2   = (const float*)d_in[4];
    const float* wdg1 = (const float*)d_in[5];
    const float* bdg1 = (const float*)d_in[6];
    const float* wdg2 = (const float*)d_in[7];
    const float* bdg2 = (const float*)d_in[8];
    const float* wsn1 = (const float*)d_in[9];
    const float* bsn1 = (const float*)d_in[10];
    const float* w3   = (const float*)d_in[11];
    const float* b3   = (const float*)d_in[12];
    float* out = (float*)d_out;

    cudaFuncSetAttribute((const void*)phase2_kernel,      cudaFuncAttributeMaxDynamicSharedMemorySize, KM_SMEM);
    cudaFuncSetAttribute((const void*)edge2_kernel,       cudaFuncAttributeMaxDynamicSharedMemorySize, E2_SMEM);
    cudaFuncSetAttribute((const void*)precomp_mma_kernel, cudaFuncAttributeMaxDynamicSharedMemorySize, FG_SMEM);
    cudaFuncSetAttribute((const void*)fgemm_mma_kernel,   cudaFuncAttributeMaxDynamicSharedMemorySize, FG_SMEM);

    void *p_A1, *p_C1, *p_A3, *p_C3, *p_idx1, *p_idx2;
    void *p_cath, *p_catl, *p_w3h, *p_w3l, *p_wsnh, *p_wsnl;
    cudaGetSymbolAddress(&p_A1,   d_A1);
    cudaGetSymbolAddress(&p_C1,   d_C1);
    cudaGetSymbolAddress(&p_A3,   d_A3);
    cudaGetSymbolAddress(&p_C3,   d_C3);
    cudaGetSymbolAddress(&p_idx1, d_idx1);
    cudaGetSymbolAddress(&p_idx2, d_idx2);
    cudaGetSymbolAddress(&p_cath, d_cath);
    cudaGetSymbolAddress(&p_catl, d_catl);
    cudaGetSymbolAddress(&p_w3h,  d_w3h);
    cudaGetSymbolAddress(&p_w3l,  d_w3l);
    cudaGetSymbolAddress(&p_wsnh, d_wsnh);
    cudaGetSymbolAddress(&p_wsnl, d_wsnl);

    // phase 1: mlp || w3 split || wsn split
    phase1_kernel<<<768, 256>>>(x, w1, b1, w2, b2, w3, wsn1);

    // phase 2: knn64 || knn3 || precomp64
    phase2_kernel<<<1172, 256, KM_SMEM>>>(x, wdg1, bdg1);

    edge2_kernel<<<148, 256, E2_SMEM>>>(
        (const float*)p_A1, (const float*)p_C1, (const int*)p_idx1, wdg2, bdg2,
        (__nv_bfloat16*)p_cath, (__nv_bfloat16*)p_catl);

    precomp_mma_kernel<<<dim3(NP/128, 4), 256, FG_SMEM>>>(
        (const __nv_bfloat16*)p_cath, (const __nv_bfloat16*)p_catl,
        (const __nv_bfloat16*)p_wsnh, (const __nv_bfloat16*)p_wsnl,
        bsn1, (float*)p_A3, (float*)p_C3);

    edge3_kernel<<<512, 256>>>((const float*)p_A3, (const float*)p_C3, (const int*)p_idx2,
        (__nv_bfloat16*)p_cath, (__nv_bfloat16*)p_catl);

    fgemm_mma_kernel<<<dim3(NP/128, 8), 256, FG_SMEM>>>(
        (const __nv_bfloat16*)p_cath, (const __nv_bfloat16*)p_catl,
        (const __nv_bfloat16*)p_w3h,  (const __nv_bfloat16*)p_w3l, b3, out);
}

// round 16
// speedup vs baseline: 1.5828x; 1.0126x over previous
#include <cuda_runtime.h>
#include <cuda_bf16.h>
#include <cstdint>

#define BB 8
#define NN 4096
#define NP (BB*NN)
#define KK 20

typedef unsigned long long ull;
typedef unsigned short ushort_t;

__device__ __forceinline__ ull pk2(float a, float b){ ull r; asm("mov.b64 %0, {%1,%2};" : "=l"(r) : "f"(a), "f"(b)); return r; }
__device__ __forceinline__ ull fma2(ull a, ull b, ull c){ ull d; asm("fma.rn.f32x2 %0, %1, %2, %3;" : "=l"(d) : "l"(a), "l"(b), "l"(c)); return d; }
__device__ __forceinline__ void upk(ull v, float& a, float& b){ asm("mov.b64 {%0,%1}, %2;" : "=f"(a), "=f"(b) : "l"(v)); }

__device__ __forceinline__ uint32_t smem_u32(const void* p) {
    uint32_t a;
    asm("{ .reg .u64 tmp; cvta.to.shared.u64 tmp, %1; cvt.u32.u64 %0, tmp; }" : "=r"(a) : "l"(p));
    return a;
}
__device__ __forceinline__ void ldmx4(uint32_t* r, uint32_t addr) {
    asm volatile("ldmatrix.sync.aligned.m8n8.x4.shared.b16 {%0,%1,%2,%3}, [%4];"
        : "=r"(r[0]), "=r"(r[1]), "=r"(r[2]), "=r"(r[3]) : "r"(addr));
}
__device__ __forceinline__ void mma16816(float* d, const uint32_t* a, const uint32_t* b) {
    asm volatile("mma.sync.aligned.m16n8k16.row.col.f32.bf16.bf16.f32 "
        "{%0,%1,%2,%3}, {%4,%5,%6,%7}, {%8,%9}, {%0,%1,%2,%3};"
        : "+f"(d[0]), "+f"(d[1]), "+f"(d[2]), "+f"(d[3])
        : "r"(a[0]), "r"(a[1]), "r"(a[2]), "r"(a[3]), "r"(b[0]), "r"(b[1]));
}
__device__ __forceinline__ void bf16split(float v, __nv_bfloat16& h, __nv_bfloat16& l) {
    h = __float2bfloat16_rn(v);
    l = __float2bfloat16_rn(v - __bfloat162float(h));
}

// ---------------- scratch -------------------------------------------------------
__device__ float d_h[NP*64];
__device__ __nv_bfloat16 d_hh[NP*64];
__device__ __nv_bfloat16 d_hl[NP*64];
__device__ float d_hsq[NP];
__device__ float d_xsq[NP];
__device__ int   d_idx1[NP*KK];
__device__ int   d_idx2[NP*KK];
__device__ float d_A1[NP*128];
__device__ float d_C1[NP*128];
__device__ float d_A3[(size_t)NP*256];
__device__ float d_C3[(size_t)NP*256];
__device__ __nv_bfloat16 d_cath[(size_t)NP*512];
__device__ __nv_bfloat16 d_catl[(size_t)NP*512];
__device__ __nv_bfloat16 d_w3h[1024*512];
__device__ __nv_bfloat16 d_w3l[1024*512];
__device__ __nv_bfloat16 d_wsnh[512*128];
__device__ __nv_bfloat16 d_wsnl[512*128];

// ================= phase 1 bodies ===============================================
__device__ void mlp_body(int blk,
    const float* __restrict__ x, const float* __restrict__ w1, const float* __restrict__ b1,
    const float* __restrict__ w2, const float* __restrict__ b2)
{
    __shared__ float w1s[192], b1s[64], b2s[64], w2s[4096];
    int t = threadIdx.x;
    for (int i = t; i < 192; i += 256) w1s[i] = w1[i];
    if (t < 64) { b1s[t] = b1[t]; b2s[t] = b2[t]; }
    for (int i = t; i < 4096; i += 256) w2s[i] = w2[i];
    __syncthreads();
    int pt = blk * 256 + t;
    float x0 = x[pt*3+0], x1 = x[pt*3+1], x2 = x[pt*3+2];
    d_xsq[pt] = x0*x0 + x1*x1 + x2*x2;
    float h1[64];
#pragma unroll
    for (int o = 0; o < 64; o++) {
        float a = b1s[o] + w1s[o*3]*x0 + w1s[o*3+1]*x1 + w1s[o*3+2]*x2;
        h1[o] = fmaxf(a, 0.f);
    }
    float sq = 0.f;
#pragma unroll 2
    for (int o = 0; o < 64; o++) {
        float a = b2s[o];
#pragma unroll
        for (int c = 0; c < 64; c++) a += w2s[o*64+c] * h1[c];
        a = fmaxf(a, 0.f);
        d_h[(size_t)pt*64 + o] = a;
        __nv_bfloat16 h, l; bf16split(a, h, l);
        d_hh[(size_t)pt*64 + o] = h;
        d_hl[(size_t)pt*64 + o] = l;
        sq += a*a;
    }
    d_hsq[pt] = sq;
}

__device__ void cvt_split_body(int blk, const float* __restrict__ src,
    __nv_bfloat16* __restrict__ hi, __nv_bfloat16* __restrict__ lo)
{
    int i = (blk * 256 + threadIdx.x) * 4;
    float4 v = *(const float4*)&src[i];
    __nv_bfloat16 h0, h1, h2, h3, l0, l1, l2, l3;
    bf16split(v.x, h0, l0); bf16split(v.y, h1, l1);
    bf16split(v.z, h2, l2); bf16split(v.w, h3, l3);
    __nv_bfloat162* hp = (__nv_bfloat162*)&hi[i];
    __nv_bfloat162* lp = (__nv_bfloat162*)&lo[i];
    hp[0] = __nv_bfloat162(h0, h1); hp[1] = __nv_bfloat162(h2, h3);
    lp[0] = __nv_bfloat162(l0, l1); lp[1] = __nv_bfloat162(l2, l3);
}

__device__ void wsn_split_body(int blk, const float* __restrict__ wsn1,
    __nv_bfloat16* __restrict__ wh, __nv_bfloat16* __restrict__ wl)
{
    int i = blk * 256 + threadIdx.x;
    int o = i >> 7, c = i & 127;
    float va = wsn1[o*256 + c];
    float vb = wsn1[o*256 + 128 + c];
    __nv_bfloat16 h, l;
    bf16split(va, h, l);
    wh[o*128 + c] = h; wl[o*128 + c] = l;
    bf16split(vb - va, h, l);
    wh[(256 + o)*128 + c] = h; wl[(256 + o)*128 + c] = l;
}

__global__ __launch_bounds__(256) void phase1_kernel(
    const float* __restrict__ x, const float* __restrict__ w1, const float* __restrict__ b1,
    const float* __restrict__ w2, const float* __restrict__ b2,
    const float* __restrict__ w3, const float* __restrict__ wsn1)
{
    int blk = blockIdx.x;
    if (blk < 128)      mlp_body(blk, x, w1, b1, w2, b2);
    else if (blk < 640) cvt_split_body(blk - 128, w3, d_w3h, d_w3l);
    else                wsn_split_body(blk - 640, wsn1, d_wsnh, d_wsnl);
}

// ================= phase 2 bodies ===============================================
// ---- knn64 via mma (staged ds, gated scan, register-prefetched tiles) ----
#define KM_QPAD 72
#define KM_QH 0
#define KM_QL (64*KM_QPAD*2)
#define KM_CH (2*64*KM_QPAD*2)
#define KM_CL (3*64*KM_QPAD*2)
#define KM_QXX (4*64*KM_QPAD*2)
#define KM_CXX (KM_QXX + 256)
#define KM_DS  (KM_CXX + 256)
#define KM_SV  (KM_DS + 64*68*4)
#define KM_BV  (KM_SV + 20*256*4)
#define KM_SI  (KM_BV + 16*256*4)
#define KM_BI  (KM_SI + 20*256*2)
#define KM_SMEM (KM_BI + 16*256*2)

__device__ void knn64_body(char* kms, int blk,
    const __nv_bfloat16* __restrict__ hh, const __nv_bfloat16* __restrict__ hl,
    const float* __restrict__ sq, int* __restrict__ out)
{
    const int QT = 64, CT = 64;
    __nv_bfloat16* qh = (__nv_bfloat16*)(kms + KM_QH);
    __nv_bfloat16* ql = (__nv_bfloat16*)(kms + KM_QL);
    __nv_bfloat16* ch = (__nv_bfloat16*)(kms + KM_CH);
    __nv_bfloat16* cl = (__nv_bfloat16*)(kms + KM_CL);
    float* qxx = (float*)(kms + KM_QXX);
    float* cxx = (float*)(kms + KM_CXX);
    float* ds  = (float*)(kms + KM_DS);
    float* sv  = (float*)(kms + KM_SV);
    float* bv  = (float*)(kms + KM_BV);
    ushort_t* si = (ushort_t*)(kms + KM_SI);
    ushort_t* bi = (ushort_t*)(kms + KM_BI);

    int b  = blk / (NN/QT);
    int q0 = (blk % (NN/QT)) * QT;
    int t = threadIdx.x, lane = t & 31, warp = t >> 5;
    int qq = t >> 2, s = t & 3;
    int wm = warp & 3, wn = warp >> 2;
    int a_row = wm*16 + (lane & 15), a_col = (lane >> 4) * 8;
    int b_row = wn*32 + (lane & 7) + ((lane >> 4) ? 8 : 0);
    int b_col = ((lane >> 3) & 1) * 8;
    uint32_t uQh = smem_u32(qh), uQl = smem_u32(ql);
    uint32_t uCh = smem_u32(ch), uCl = smem_u32(cl);

    for (int i = t; i < 64*8; i += 256) {
        int r = i >> 3, c = (i & 7) * 8;
        size_t gi = (size_t)(b*NN + q0 + r)*64 + c;
        *(uint4*)&qh[r*KM_QPAD + c] = *(const uint4*)&hh[gi];
        *(uint4*)&ql[r*KM_QPAD + c] = *(const uint4*)&hl[gi];
    }
    if (t < QT) qxx[t] = sq[b*NN + q0 + t];

#pragma unroll
    for (int r = 0; r < KK; r++) { sv[r*256 + t] = -3.4e38f; si[r*256 + t] = 0xFFFF; }
    float minv = -3.4e38f; int minp = 0;
    float gthr = -3.4e38f;

    // per-thread row/col for tile staging (2 chunks/thread)
    int pr0 = t >> 3,           pc0 = (t & 7) * 8;
    int pr1 = (t + 256) >> 3,   pc1 = ((t + 256) & 7) * 8;

    // prefetch tile 0 into registers
    uint4 pfh0, pfh1, pfl0, pfl1;
    {
        size_t g0 = (size_t)(b*NN + pr0)*64 + pc0;
        size_t g1 = (size_t)(b*NN + pr1)*64 + pc1;
        pfh0 = *(const uint4*)&hh[g0]; pfl0 = *(const uint4*)&hl[g0];
        pfh1 = *(const uint4*)&hh[g1]; pfl1 = *(const uint4*)&hl[g1];
    }
    float cxx_reg = (t < CT) ? sq[b*NN + t] : 0.f;

    for (int tile = 0; tile < NN/CT; tile++) {
        __syncthreads();
        // store prefetched tile into smem
        *(uint4*)&ch[pr0*KM_QPAD + pc0] = pfh0;
        *(uint4*)&cl[pr0*KM_QPAD + pc0] = pfl0;
        *(uint4*)&ch[pr1*KM_QPAD + pc1] = pfh1;
        *(uint4*)&cl[pr1*KM_QPAD + pc1] = pfl1;
        if (t < CT) cxx[t] = cxx_reg;
        // issue prefetch for next tile (latency hidden behind mma+scan)
        if (tile + 1 < NN/CT) {
            int base = (tile + 1) * CT;
            size_t g0 = (size_t)(b*NN + base + pr0)*64 + pc0;
            size_t g1 = (size_t)(b*NN + base + pr1)*64 + pc1;
            pfh0 = *(const uint4*)&hh[g0]; pfl0 = *(const uint4*)&hl[g0];
            pfh1 = *(const uint4*)&hh[g1]; pfl1 = *(const uint4*)&hl[g1];
            if (t < CT) cxx_reg = sq[b*NN + base + t];
        }
        __syncthreads();

        float acc[4][4];
#pragma unroll
        for (int ni = 0; ni < 4; ni++)
#pragma unroll
            for (int e = 0; e < 4; e++) acc[ni][e] = 0.f;
#pragma unroll
        for (int ks = 0; ks < 4; ks++) {
            int k0 = ks * 16;
            uint32_t ah[4], al[4];
            uint32_t offA = (uint32_t)((a_row*KM_QPAD + a_col + k0) * 2);
            ldmx4(ah, uQh + offA);
            ldmx4(al, uQl + offA);
#pragma unroll
            for (int j = 0; j < 2; j++) {
                uint32_t bh[4], bl[4];
                uint32_t offB = (uint32_t)(((b_row + j*16)*KM_QPAD + b_col + k0) * 2);
                ldmx4(bh, uCh + offB);
                ldmx4(bl, uCl + offB);
#pragma unroll
                for (int sub = 0; sub < 2; sub++) {
                    int ni = j*2 + sub;
                    mma16816(acc[ni], ah, bh + sub*2);
                    mma16816(acc[ni], ah, bl + sub*2);
                    mma16816(acc[ni], al, bh + sub*2);
                }
            }
        }
        {
            int r = lane >> 2, c2 = (lane & 3) * 2;
            int row0 = wm*16 + r, row1 = row0 + 8;
            float qx0 = qxx[row0], qx1 = qxx[row1];
#pragma unroll
            for (int ni = 0; ni < 4; ni++) {
                int col = wn*32 + ni*8 + c2;
                float cx0 = cxx[col], cx1 = cxx[col+1];
                float2 v0, v1;
                v0.x = 2.f*acc[ni][0] - qx0 - cx0; v0.y = 2.f*acc[ni][1] - qx0 - cx1;
                v1.x = 2.f*acc[ni][2] - qx1 - cx0; v1.y = 2.f*acc[ni][3] - qx1 - cx1;
                *(float2*)&ds[row0*68 + col] = v0;
                *(float2*)&ds[row1*68 + col] = v1;
            }
        }
        __syncthreads();

        int cnt = 0;
        const float* row = &ds[qq*68 + s*16];
        int base = tile*CT + s*16;
#pragma unroll
        for (int c4 = 0; c4 < 4; c4++) {
            float4 v = *(const float4*)&row[c4*4];
            float m = fmaxf(fmaxf(v.x, v.y), fmaxf(v.z, v.w));
            if (m > gthr) {
                int id0 = base + c4*4;
                if (v.x > gthr) { bv[cnt*256+t] = v.x; bi[cnt*256+t] = (ushort_t)(id0  ); cnt++; }
                if (v.y > gthr) { bv[cnt*256+t] = v.y; bi[cnt*256+t] = (ushort_t)(id0+1); cnt++; }
                if (v.z > gthr) { bv[cnt*256+t] = v.z; bi[cnt*256+t] = (ushort_t)(id0+2); cnt++; }
                if (v.w > gthr) { bv[cnt*256+t] = v.w; bi[cnt*256+t] = (ushort_t)(id0+3); cnt++; }
            }
        }
        for (int j = 0; __any_sync(0xffffffffu, j < cnt); j++) {
            if (j < cnt) {
                float d = bv[j*256+t];
                if (d > minv) {
                    sv[minp*256+t] = d; si[minp*256+t] = bi[j*256+t];
                    float mv = sv[t]; int mp = 0;
#pragma unroll
                    for (int r = 1; r < KK; r++) {
                        float x = sv[r*256+t];
                        if (x < mv) { mv = x; mp = r; }
                    }
                    minv = mv; minp = mp;
                }
            }
        }
        float m = minv;
        m = fmaxf(m, __shfl_xor_sync(0xffffffffu, m, 1));
        m = fmaxf(m, __shfl_xor_sync(0xffffffffu, m, 2));
        gthr = m;
    }

#pragma unroll 1
    for (int r = 0; r < KK; r++) {
        float bvv = -3.4e38f; int bid = 0x7fffffff; int bslot = 0;
#pragma unroll
        for (int rr = 0; rr < KK; rr++) {
            float x = sv[rr*256+t]; int xi = si[rr*256+t];
            bool better = (x > bvv) || (x == bvv && xi < bid);
            if (better) { bvv = x; bid = xi; bslot = rr; }
        }
        float v = bvv; int id = bid; int sl = s;
#pragma unroll
        for (int off = 1; off <= 2; off <<= 1) {
            float ov = __shfl_xor_sync(0xffffffffu, v, off);
            int  oid = __shfl_xor_sync(0xffffffffu, id, off);
            int  osl = __shfl_xor_sync(0xffffffffu, sl, off);
            if (ov > v || (ov == v && oid < id)) { v = ov; id = oid; sl = osl; }
        }
        if (sl == s) sv[bslot*256+t] = -3.4e38f;
        if (s == 0) out[((size_t)(b*NN + q0 + qq))*KK + r] = id;
    }
}

// ---- knn small-C (f32x2, staged ds, gated scan) ----
template<int C>
__device__ void knn_small_body(float* km, int blk,
    const float* __restrict__ data, const float* __restrict__ sq, int* __restrict__ out)
{
    const int QT = 64, CT = 64;
    const int QDUP_F = (C*130 + 3) & ~3;
    ull*   qdup = (ull*)km;
    float* csT  = km + QDUP_F;
    float* ds   = csT + C*68;
    float* qxx  = ds + 64*68;
    float* cxx  = qxx + 64;
    float* sv   = cxx + 64;
    float* bv   = sv + 20*256;
    ushort_t* si = (ushort_t*)(bv + 16*256);
    ushort_t* bi = si + 20*256;

    int b  = blk / (NN/QT);
    int q0 = (blk % (NN/QT)) * QT;
    int t = threadIdx.x;
    int tq = t >> 4, tc = t & 15;
    int qq = t >> 2, s = t & 3;

    for (int i = t; i < QT*C; i += 256) {
        int q = i / C, d = i - q*C;
        float v = data[((size_t)(b*NN + q0 + q))*C + d];
        qdup[d*65 + q] = pk2(v, v);
    }
    if (t < QT) qxx[t] = sq[b*NN + q0 + t];

#pragma unroll
    for (int r = 0; r < KK; r++) { sv[r*256 + t] = -3.4e38f; si[r*256 + t] = 0xFFFF; }
    float minv = -3.4e38f; int minp = 0;
    float gthr = -3.4e38f;

    for (int tile = 0; tile < NN/CT; tile++) {
        __syncthreads();
        for (int i = t; i < CT*C; i += 256) {
            int cth = i / C, d = i - cth*C;
            csT[d*68 + cth] = data[((size_t)(b*NN + tile*CT + cth))*C + d];
        }
        if (t < CT) cxx[t] = sq[b*NN + tile*CT + t];
        __syncthreads();

        ull a00=0,a01=0,a10=0,a11=0,a20=0,a21=0,a30=0,a31=0;
#pragma unroll 8
        for (int k = 0; k < C; k++) {
            ulonglong2 cp = *(const ulonglong2*)&csT[k*68 + tc*4];
            const ull* qd = &qdup[k*65 + tq*4];
            ull q0d = qd[0], q1d = qd[1], q2d = qd[2], q3d = qd[3];
            a00 = fma2(q0d, cp.x, a00); a01 = fma2(q0d, cp.y, a01);
            a10 = fma2(q1d, cp.x, a10); a11 = fma2(q1d, cp.y, a11);
            a20 = fma2(q2d, cp.x, a20); a21 = fma2(q2d, cp.y, a21);
            a30 = fma2(q3d, cp.x, a30); a31 = fma2(q3d, cp.y, a31);
        }
        float cx0 = cxx[tc*4], cx1 = cxx[tc*4+1], cx2 = cxx[tc*4+2], cx3 = cxx[tc*4+3];
        ull accs[4][2] = {{a00,a01},{a10,a11},{a20,a21},{a30,a31}};
#pragma unroll
        for (int i = 0; i < 4; i++) {
            float qx = qxx[tq*4 + i];
            float d0, d1, d2, d3;
            upk(accs[i][0], d0, d1); upk(accs[i][1], d2, d3);
            float4 r;
            r.x = 2.f*d0 - qx - cx0; r.y = 2.f*d1 - qx - cx1;
            r.z = 2.f*d2 - qx - cx2; r.w = 2.f*d3 - qx - cx3;
            *(float4*)&ds[(tq*4 + i)*68 + tc*4] = r;
        }
        __syncthreads();

        int cnt = 0;
        const float* row = &ds[qq*68 + s*16];
        int base = tile*CT + s*16;
#pragma unroll
        for (int c4 = 0; c4 < 4; c4++) {
            float4 v = *(const float4*)&row[c4*4];
            float m = fmaxf(fmaxf(v.x, v.y), fmaxf(v.z, v.w));
            if (m > gthr) {
                int id0 = base + c4*4;
                if (v.x > gthr) { bv[cnt*256+t] = v.x; bi[cnt*256+t] = (ushort_t)(id0  ); cnt++; }
                if (v.y > gthr) { bv[cnt*256+t] = v.y; bi[cnt*256+t] = (ushort_t)(id0+1); cnt++; }
                if (v.z > gthr) { bv[cnt*256+t] = v.z; bi[cnt*256+t] = (ushort_t)(id0+2); cnt++; }
                if (v.w > gthr) { bv[cnt*256+t] = v.w; bi[cnt*256+t] = (ushort_t)(id0+3); cnt++; }
            }
        }
        for (int j = 0; __any_sync(0xffffffffu, j < cnt); j++) {
            if (j < cnt) {
                float d = bv[j*256+t];
                if (d > minv) {
                    sv[minp*256+t] = d; si[minp*256+t] = bi[j*256+t];
                    float mv = sv[t]; int mp = 0;
#pragma unroll
                    for (int r = 1; r < KK; r++) {
                        float x = sv[r*256+t];
                        if (x < mv) { mv = x; mp = r; }
                    }
                    minv = mv; minp = mp;
                }
            }
        }
        float m = minv;
        m = fmaxf(m, __shfl_xor_sync(0xffffffffu, m, 1));
        m = fmaxf(m, __shfl_xor_sync(0xffffffffu, m, 2));
        gthr = m;
    }

#pragma unroll 1
    for (int r = 0; r < KK; r++) {
        float bvv = -3.4e38f; int bid = 0x7fffffff; int bslot = 0;
#pragma unroll
        for (int rr = 0; rr < KK; rr++) {
            float x = sv[rr*256+t]; int xi = si[rr*256+t];
            bool better = (x > bvv) || (x == bvv && xi < bid);
            if (better) { bvv = x; bid = xi; bslot = rr; }
        }
        float v = bvv; int id = bid; int sl = s;
#pragma unroll
        for (int off = 1; off <= 2; off <<= 1) {
            float ov = __shfl_xor_sync(0xffffffffu, v, off);
            int  oid = __shfl_xor_sync(0xffffffffu, id, off);
            int  osl = __shfl_xor_sync(0xffffffffu, sl, off);
            if (ov > v || (ov == v && oid < id)) { v = ov; id = oid; sl = osl; }
        }
        if (sl == s) sv[bslot*256+t] = -3.4e38f;
        if (s == 0) out[((size_t)(b*NN + q0 + qq))*KK + r] = id;
    }
}

// ---- precomp64 (f32x2) ----
__device__ void precomp64_body(float* sm, int blk, int nblk,
    const float* __restrict__ in,
    const float* __restrict__ W, const float* __restrict__ bias,
    float* __restrict__ A, float* __restrict__ Cc)
{
    const int CIN = 64;
    float* wa = sm;
    float* wd = sm + CIN*128;
    ull* invd = (ull*)(sm + 2*CIN*128);
    int t = threadIdx.x;
    int to = t & 31, rr = (t >> 5) & 1, pp = t >> 6;
    int o4 = 4*to;

    for (int i = t; i < 128*2*CIN; i += 256) {
        int oo = i / (2*CIN), c = i - oo*(2*CIN);
        float v = W[i];
        if (c < CIN) wa[c*128 + oo] = v; else wd[(c-CIN)*128 + oo] = v;
    }
    __syncthreads();
    for (int i = t; i < CIN*128; i += 256) wd[i] -= wa[i];
    ull bb0 = 0, bb1 = 0;
    if (rr) { bb0 = pk2(bias[o4], bias[o4+1]); bb1 = pk2(bias[o4+2], bias[o4+3]); }
    const float* src = rr ? wd : wa;
    float* dst = rr ? Cc : A;
    __syncthreads();

    for (int grp = blk; grp < NP/8; grp += nblk) {
        __syncthreads();
        for (int i = t; i < 8*CIN; i += 256) {
            int c = i & (CIN-1), p = i >> 6;
            float v = in[(size_t)(grp*8 + p)*64 + c];
            invd[c*8 + p] = pk2(v, v);
        }
        __syncthreads();
        ull acc[2][2] = {{bb0, bb1}, {bb0, bb1}};
#pragma unroll 4
        for (int c = 0; c < CIN; c++) {
            ulonglong2 wp = *(const ulonglong2*)&src[c*128 + o4];
            ull iv0 = invd[c*8 + 2*pp], iv1 = invd[c*8 + 2*pp + 1];
            acc[0][0] = fma2(wp.x, iv0, acc[0][0]);
            acc[0][1] = fma2(wp.y, iv0, acc[0][1]);
            acc[1][0] = fma2(wp.x, iv1, acc[1][0]);
            acc[1][1] = fma2(wp.y, iv1, acc[1][1]);
        }
#pragma unroll
        for (int pt = 0; pt < 2; pt++) {
            size_t base = (size_t)(grp*8 + 2*pp + pt)*128 + o4;
            *(ull*)&dst[base]     = acc[pt][0];
            *(ull*)&dst[base + 2] = acc[pt][1];
        }
    }
}

__global__ __launch_bounds__(256, 2) void phase2_kernel(
    const float* __restrict__ x,
    const float* __restrict__ wdg1, const float* __restrict__ bdg1)
{
    extern __shared__ char dsm[];
    int blk = blockIdx.x;
    if (blk < 512)
        knn64_body(dsm, blk, d_hh, d_hl, d_hsq, d_idx1);
    else if (blk < 1024)
        knn_small_body<3>((float*)dsm, blk - 512, x, d_xsq, d_idx2);
    else
        precomp64_body((float*)dsm, blk - 1024, 148, d_h, wdg1, bdg1, d_A1, d_C1);
}

// ---------------- kernel 4: fused edge-conv1 + edge-conv2 via mma.sync -----------
#define E2_CPAD 136
#define E2_SPAD 132
#define E2_WH 0
#define E2_WL (128*E2_CPAD*2)
#define E2_G  (E2_WL + 128*E2_CPAD*2)
#define E2_GL_OFF (160*E2_CPAD*2)
#define E2_C1 (E2_G + 2*160*E2_CPAD*2)
#define E2_PX1 (E2_C1 + 1024*4)
#define E2_B2 (E2_PX1 + 4096*4)
#define E2_IXS (E2_B2 + 512)
#define E2_SMEM (E2_IXS + 640)

__global__ __launch_bounds__(256) void edge2_kernel(
    const float* __restrict__ A1, const float* __restrict__ C1,
    const int* __restrict__ idx, const float* __restrict__ w2,
    const float* __restrict__ b2,
    __nv_bfloat16* __restrict__ cath, __nv_bfloat16* __restrict__ catl)
{
    extern __shared__ char esm[];
    __nv_bfloat16* wh = (__nv_bfloat16*)(esm + E2_WH);
    __nv_bfloat16* wl = (__nv_bfloat16*)(esm + E2_WL);
    __nv_bfloat16* gh = (__nv_bfloat16*)(esm + E2_G);
    __nv_bfloat16* gl = (__nv_bfloat16*)(esm + E2_G + E2_GL_OFF);
    float* stage = (float*)(esm + E2_G);
    float* c1s = (float*)(esm + E2_C1);
    float* px1 = (float*)(esm + E2_PX1);
    float* b2s = (float*)(esm + E2_B2);
    int*   ixs = (int*)(esm + E2_IXS);

    int t = threadIdx.x, lane = t & 31, warp = t >> 5;
    for (int i = t; i < 128*128; i += 256) {
        float v = w2[i];
        __nv_bfloat16 h, l; bf16split(v, h, l);
        int o = i >> 7, c = i & 127;
        wh[o*E2_CPAD + c] = h; wl[o*E2_CPAD + c] = l;
    }
    if (t < 128) b2s[t] = b2[t];
    __syncthreads();

    int cc  = t & 127, hh  = t >> 7;
    int ccp = t & 63,  hh4 = t >> 6;
    int wm = warp & 1, wn = warp >> 1;
    int m0 = wm * 80, o0w = wn * 32;
    int a_row = m0 + (lane & 15), a_col = (lane >> 4) * 8;
    int b_row = o0w + (lane & 7) + ((lane >> 4) ? 8 : 0);
    int b_col = ((lane >> 3) & 1) * 8;
    uint32_t uGh = smem_u32(gh), uGl = smem_u32(gl);
    uint32_t uWh = smem_u32(wh), uWl = smem_u32(wl);

    for (int grp = blockIdx.x; grp < NP/8; grp += gridDim.x) {
        int pt0 = grp * 8;
        int b = pt0 / NN;
        __syncthreads();
        for (int i = t; i < 1024; i += 256) c1s[i] = C1[(size_t)pt0*128 + i];
        if (t < 160) { int p = t / 20, k = t - p*20; ixs[t] = idx[(size_t)(pt0+p)*KK + k]; }
        __syncthreads();

#pragma unroll
        for (int p = 0; p < 8; p++) {
            float2 cv = *(const float2*)&c1s[p*128 + ccp*2];
            float mx = -3.4e38f, my = -3.4e38f;
#pragma unroll
            for (int k = 0; k < 5; k++) {
                int pk = p*20 + hh4 + 4*k;
                float2 a = *(const float2*)&A1[((size_t)(b*NN + ixs[pk]))*128 + ccp*2];
                float g0 = fmaxf(a.x + cv.x, 0.f);
                float g1 = fmaxf(a.y + cv.y, 0.f);
                __nv_bfloat16 h0, l0, h1, l1;
                bf16split(g0, h0, l0); bf16split(g1, h1, l1);
                *(__nv_bfloat162*)&gh[pk*E2_CPAD + ccp*2] = __nv_bfloat162(h0, h1);
                *(__nv_bfloat162*)&gl[pk*E2_CPAD + ccp*2] = __nv_bfloat162(l0, l1);
                mx = fmaxf(mx, g0); my = fmaxf(my, g1);
            }
            float2 pm; pm.x = mx; pm.y = my;
            *(float2*)&px1[(hh4*8 + p)*128 + ccp*2] = pm;
        }
        __syncthreads();

#pragma unroll
        for (int pi = 0; pi < 4; pi++) {
            int p = hh*4 + pi;
            float x1 = fmaxf(fmaxf(px1[p*128 + cc], px1[1024 + p*128 + cc]),
                             fmaxf(px1[2048 + p*128 + cc], px1[3072 + p*128 + cc]));
            size_t ci = (size_t)(pt0+p)*512 + cc;
            __nv_bfloat16 h, l; bf16split(x1, h, l);
            cath[ci] = h; catl[ci] = l;
        }

        float acc[5][4][4];
#pragma unroll
        for (int mi = 0; mi < 5; mi++)
#pragma unroll
            for (int ni = 0; ni < 4; ni++)
#pragma unroll
                for (int e = 0; e < 4; e++) acc[mi][ni][e] = 0.f;
#pragma unroll
        for (int ks = 0; ks < 8; ks++) {
            int k0 = ks * 16;
            uint32_t ah[5][4], al[5][4];
#pragma unroll
            for (int mi = 0; mi < 5; mi++) {
                uint32_t off = (uint32_t)(((a_row + mi*16)*E2_CPAD + a_col + k0) * 2);
                ldmx4(ah[mi], uGh + off);
                ldmx4(al[mi], uGl + off);
            }
            uint32_t bh[2][4], bl[2][4];
#pragma unroll
            for (int j = 0; j < 2; j++) {
                uint32_t off = (uint32_t)(((b_row + j*16)*E2_CPAD + b_col + k0) * 2);
                ldmx4(bh[j], uWh + off);
                ldmx4(bl[j], uWl + off);
            }
#pragma unroll
            for (int mi = 0; mi < 5; mi++)
#pragma unroll
                for (int j = 0; j < 2; j++)
#pragma unroll
                    for (int sub = 0; sub < 2; sub++) {
                        int ni = j*2 + sub;
                        mma16816(acc[mi][ni], ah[mi], bh[j] + sub*2);
                        mma16816(acc[mi][ni], ah[mi], bl[j] + sub*2);
                        mma16816(acc[mi][ni], al[mi], bh[j] + sub*2);
                    }
        }
        __syncthreads();

        int r = lane >> 2, c2 = (lane & 3) * 2;
#pragma unroll
        for (int mi = 0; mi < 5; mi++)
#pragma unroll
            for (int ni = 0; ni < 4; ni++) {
                int row = m0 + mi*16 + r;
                int o = o0w + ni*8 + c2;
                stage[row*E2_SPAD + o]       = acc[mi][ni][0];
                stage[row*E2_SPAD + o + 1]   = acc[mi][ni][1];
                stage[(row+8)*E2_SPAD + o]   = acc[mi][ni][2];
                stage[(row+8)*E2_SPAD + o+1] = acc[mi][ni][3];
            }
        __syncthreads();

#pragma unroll
        for (int pi = 0; pi < 4; pi++) {
            int p = hh*4 + pi;
            float m = -3.4e38f;
#pragma unroll 4
            for (int k = 0; k < 20; k++) m = fmaxf(m, stage[(p*20 + k)*E2_SPAD + cc]);
            float x2 = fmaxf(m + b2s[cc], 0.f);
            size_t ci = (size_t)(pt0+p)*512 + 128 + cc;
            __nv_bfloat16 h, l; bf16split(x2, h, l);
            cath[ci] = h; catl[ci] = l;
        }
    }
}

// ---------------- precomp A3/C3 via mma.sync 3-term ------------------------------
#define FG_PAD 72
#define FG_SMEM (4*128*FG_PAD*2)

__global__ __launch_bounds__(256) void precomp_mma_kernel(
    const __nv_bfloat16* __restrict__ catH, const __nv_bfloat16* __restrict__ catL,
    const __nv_bfloat16* __restrict__ wH,   const __nv_bfloat16* __restrict__ wL,
    const float* __restrict__ bias, float* __restrict__ A3, float* __restrict__ C3)
{
    extern __shared__ char psm[];
    __nv_bfloat16* Ah = (__nv_bfloat16*)psm;
    __nv_bfloat16* Al = Ah + 128*FG_PAD;
    __nv_bfloat16* Bh = Al + 128*FG_PAD;
    __nv_bfloat16* Bl = Bh + 128*FG_PAD;
    __shared__ float bs[128];
    int t = threadIdx.x, lane = t & 31, warp = t >> 5;
    int wm = warp & 3, wn = warp >> 2;
    int pt0 = blockIdx.x * 128;
    int o0  = blockIdx.y * 128;
    bool isC = (o0 >= 256);
    if (t < 128) bs[t] = isC ? bias[o0 - 256 + t] : 0.f;

    float acc[2][8][4];
#pragma unroll
    for (int mi = 0; mi < 2; mi++)
#pragma unroll
        for (int ni = 0; ni < 8; ni++)
#pragma unroll
            for (int e = 0; e < 4; e++) acc[mi][ni][e] = 0.f;

    int a_row = wm*32 + (lane & 15);
    int a_col = (lane >> 4) * 8;
    int b_row = wn*64 + (lane & 7) + ((lane >> 4) ? 8 : 0);
    int b_col = ((lane >> 3) & 1) * 8;
    uint32_t uAh = smem_u32(Ah), uAl = smem_u32(Al);
    uint32_t uBh = smem_u32(Bh), uBl = smem_u32(Bl);

    for (int kc = 0; kc < 2; kc++) {
        __syncthreads();
        for (int i = t; i < 1024; i += 256) {
            int r = i >> 3, c = (i & 7) * 8;
            size_t gA = (size_t)(pt0 + r)*512 + 128 + kc*64 + c;
            size_t gB = (size_t)(o0 + r)*128 + kc*64 + c;
            *(uint4*)&Ah[r*FG_PAD + c] = *(const uint4*)&catH[gA];
            *(uint4*)&Al[r*FG_PAD + c] = *(const uint4*)&catL[gA];
            *(uint4*)&Bh[r*FG_PAD + c] = *(const uint4*)&wH[gB];
            *(uint4*)&Bl[r*FG_PAD + c] = *(const uint4*)&wL[gB];
        }
        __syncthreads();
#pragma unroll
        for (int ks = 0; ks < 4; ks++) {
            int k0 = ks * 16;
            uint32_t ah[2][4], al[2][4];
#pragma unroll
            for (int mi = 0; mi < 2; mi++) {
                uint32_t off = (uint32_t)(((a_row + mi*16)*FG_PAD + a_col + k0) * 2);
                ldmx4(ah[mi], uAh + off);
                ldmx4(al[mi], uAl + off);
            }
#pragma unroll
            for (int j = 0; j < 4; j++) {
                uint32_t bh[4], bl[4];
                uint32_t off = (uint32_t)(((b_row + j*16)*FG_PAD + b_col + k0) * 2);
                ldmx4(bh, uBh + off);
                ldmx4(bl, uBl + off);
#pragma unroll
                for (int sub = 0; sub < 2; sub++) {
                    int ni = j*2 + sub;
#pragma unroll
                    for (int mi = 0; mi < 2; mi++) {
                        mma16816(acc[mi][ni], ah[mi], bh + sub*2);
                        mma16816(acc[mi][ni], ah[mi], bl + sub*2);
                        mma16816(acc[mi][ni], al[mi], bh + sub*2);
                    }
                }
            }
        }
    }

    __syncthreads();
    float* stage = (float*)psm;      // [128m][132o]
    int r = lane >> 2, c = (lane & 3) * 2;
#pragma unroll
    for (int mi = 0; mi < 2; mi++) {
#pragma unroll
        for (int ni = 0; ni < 8; ni++) {
            int m = wm*32 + mi*16 + r;
            int o = wn*64 + ni*8 + c;
            stage[(m  )*132 + o    ] = acc[mi][ni][0];
            stage[(m  )*132 + o + 1] = acc[mi][ni][1];
            stage[(m+8)*132 + o    ] = acc[mi][ni][2];
            stage[(m+8)*132 + o + 1] = acc[mi][ni][3];
        }
    }
    __syncthreads();
    float* dst = isC ? C3 : A3;
    int ob = o0 & 255;
    for (int i = t; i < 128*128; i += 256) {
        int m = i >> 7, o = i & 127;
        dst[(size_t)(pt0 + m)*256 + ob + o] = stage[m*132 + o] + bs[o];
    }
}

// ---------------- edge-conv3 -----------------------------------------------------
__global__ __launch_bounds__(256) void edge3_kernel(
    const float* __restrict__ A3, const float* __restrict__ C3,
    const int* __restrict__ idx,
    __nv_bfloat16* __restrict__ cath, __nv_bfloat16* __restrict__ catl)
{
    __shared__ float2 c3s[2][128];
    __shared__ int ixs[2][KK];
    int t = threadIdx.x;
    int cc = t & 127, hh = t >> 7;
    for (int grp = blockIdx.x; grp < NP/2; grp += gridDim.x) {
        int pt = grp*2 + hh;
        __syncthreads();
        c3s[hh][cc] = *(const float2*)&C3[(size_t)pt*256 + cc*2];
        if (cc < KK) ixs[hh][cc] = idx[(size_t)pt*KK + cc];
        __syncthreads();
        int b = pt / NN;
        float2 ctr = c3s[hh][cc];
        float m0 = -3.4e38f, m1 = -3.4e38f;
#pragma unroll 4
        for (int k = 0; k < KK; k++) {
            float2 a = *(const float2*)&A3[((size_t)(b*NN + ixs[hh][k]))*256 + cc*2];
            m0 = fmaxf(m0, a.x + ctr.x);
            m1 = fmaxf(m1, a.y + ctr.y);
        }
        m0 = fmaxf(m0, 0.f); m1 = fmaxf(m1, 0.f);
        size_t ci = (size_t)pt*512 + 256 + cc*2;
        __nv_bfloat16 h, l;
        bf16split(m0, h, l); cath[ci] = h;     catl[ci] = l;
        bf16split(m1, h, l); cath[ci + 1] = h; catl[ci + 1] = l;
    }
}

// ---------------- final GEMM via mma.sync bf16 hi/lo 3-term ----------------------
__global__ __launch_bounds__(256) void fgemm_mma_kernel(
    const __nv_bfloat16* __restrict__ catH, const __nv_bfloat16* __restrict__ catL,
    const __nv_bfloat16* __restrict__ w3H,  const __nv_bfloat16* __restrict__ w3L,
    const float* __restrict__ b3, float* __restrict__ out)
{
    extern __shared__ char fsm[];
    __nv_bfloat16* Ah = (__nv_bfloat16*)fsm;
    __nv_bfloat16* Al = Ah + 128*FG_PAD;
    __nv_bfloat16* Bh = Al + 128*FG_PAD;
    __nv_bfloat16* Bl = Bh + 128*FG_PAD;
    __shared__ float b3s[128];
    int t = threadIdx.x, lane = t & 31, warp = t >> 5;
    int wm = warp & 3, wn = warp >> 2;
    int n0 = blockIdx.x * 128;
    int o0 = blockIdx.y * 128;
    if (t < 128) b3s[t] = b3[o0 + t];

    float acc[2][8][4];
#pragma unroll
    for (int mi = 0; mi < 2; mi++)
#pragma unroll
        for (int ni = 0; ni < 8; ni++)
#pragma unroll
            for (int e = 0; e < 4; e++) acc[mi][ni][e] = 0.f;

    int a_row = wm*32 + (lane & 15);
    int a_col = (lane >> 4) * 8;
    int b_row = wn*64 + (lane & 7) + ((lane >> 4) ? 8 : 0);
    int b_col = ((lane >> 3) & 1) * 8;
    uint32_t uAh = smem_u32(Ah), uAl = smem_u32(Al);
    uint32_t uBh = smem_u32(Bh), uBl = smem_u32(Bl);

    for (int kc = 0; kc < 8; kc++) {
        __syncthreads();
        for (int i = t; i < 1024; i += 256) {
            int r = i >> 3, c = (i & 7) * 8;
            size_t gA = (size_t)(n0 + r)*512 + kc*64 + c;
            size_t gB = (size_t)(o0 + r)*512 + kc*64 + c;
            *(uint4*)&Ah[r*FG_PAD + c] = *(const uint4*)&catH[gA];
            *(uint4*)&Al[r*FG_PAD + c] = *(const uint4*)&catL[gA];
            *(uint4*)&Bh[r*FG_PAD + c] = *(const uint4*)&w3H[gB];
            *(uint4*)&Bl[r*FG_PAD + c] = *(const uint4*)&w3L[gB];
        }
        __syncthreads();
#pragma unroll
        for (int ks = 0; ks < 4; ks++) {
            int k0 = ks * 16;
            uint32_t ah[2][4], al[2][4];
#pragma unroll
            for (int mi = 0; mi < 2; mi++) {
                uint32_t off = (uint32_t)(((a_row + mi*16)*FG_PAD + a_col + k0) * 2);
                ldmx4(ah[mi], uAh + off);
                ldmx4(al[mi], uAl + off);
            }
#pragma unroll
            for (int j = 0; j < 4; j++) {
                uint32_t bh[4], bl[4];
                uint32_t off = (uint32_t)(((b_row + j*16)*FG_PAD + b_col + k0) * 2);
                ldmx4(bh, uBh + off);
                ldmx4(bl, uBl + off);
#pragma unroll
                for (int sub = 0; sub < 2; sub++) {
                    int ni = j*2 + sub;
#pragma unroll
                    for (int mi = 0; mi < 2; mi++) {
                        mma16816(acc[mi][ni], ah[mi], bh + sub*2);
                        mma16816(acc[mi][ni], ah[mi], bl + sub*2);
                        mma16816(acc[mi][ni], al[mi], bh + sub*2);
                    }
                }
            }
        }
    }

    __syncthreads();
    float* stage = (float*)fsm;      // [128o][132p]
    int r = lane >> 2, c = (lane & 3) * 2;
#pragma unroll
    for (int mi = 0; mi < 2; mi++) {
#pragma unroll
        for (int ni = 0; ni < 8; ni++) {
            int m = wm*32 + mi*16 + r;
            int o = wn*64 + ni*8 + c;
            stage[(o  )*132 + m    ] = acc[mi][ni][0];
            stage[(o+1)*132 + m    ] = acc[mi][ni][1];
            stage[(o  )*132 + m + 8] = acc[mi][ni][2];
            stage[(o+1)*132 + m + 8] = acc[mi][ni][3];
        }
    }
    __syncthreads();
    int b = n0 >> 12, nn = n0 & 4095;
    for (int i = t; i < 128*128; i += 256) {
        int o = i >> 7, p = i & 127;
        float v = stage[o*132 + p] + b3s[o];
        out[((size_t)(b*1024 + o0 + o))*NN + nn + p] = fmaxf(v, 0.f);
    }
}

// ---------------------------------------------------------------------------------
extern "C" void kernel_launch(void* const* d_in, const int* in_sizes, int n_in,
                              void* d_out, int out_size)
{
    const float* x    = (const float*)d_in[0];
    const float* w1   = (const float*)d_in[1];
    const float* b1   = (const float*)d_in[2];
    const float* w2   = (const float*)d_in[3];
    const float* b2   = (const float*)d_in[4];
    const float* wdg1 = (const float*)d_in[5];
    const float* bdg1 = (const float*)d_in[6];
    const float* wdg2 = (const float*)d_in[7];
    const float* bdg2 = (const float*)d_in[8];
    const float* wsn1 = (const float*)d_in[9];
    const float* bsn1 = (const float*)d_in[10];
    const float* w3   = (const float*)d_in[11];
    const float* b3   = (const float*)d_in[12];
    float* out = (float*)d_out;

    cudaFuncSetAttribute((const void*)phase2_kernel,      cudaFuncAttributeMaxDynamicSharedMemorySize, KM_SMEM);
    cudaFuncSetAttribute((const void*)edge2_kernel,       cudaFuncAttributeMaxDynamicSharedMemorySize, E2_SMEM);
    cudaFuncSetAttribute((const void*)precomp_mma_kernel, cudaFuncAttributeMaxDynamicSharedMemorySize, FG_SMEM);
    cudaFuncSetAttribute((const void*)fgemm_mma_kernel,   cudaFuncAttributeMaxDynamicSharedMemorySize, FG_SMEM);

    void *p_A1, *p_C1, *p_A3, *p_C3, *p_idx1, *p_idx2;
    void *p_cath, *p_catl, *p_w3h, *p_w3l, *p_wsnh, *p_wsnl;
    cudaGetSymbolAddress(&p_A1,   d_A1);
    cudaGetSymbolAddress(&p_C1,   d_C1);
    cudaGetSymbolAddress(&p_A3,   d_A3);
    cudaGetSymbolAddress(&p_C3,   d_C3);
    cudaGetSymbolAddress(&p_idx1, d_idx1);
    cudaGetSymbolAddress(&p_idx2, d_idx2);
    cudaGetSymbolAddress(&p_cath, d_cath);
    cudaGetSymbolAddress(&p_catl, d_catl);
    cudaGetSymbolAddress(&p_w3h,  d_w3h);
    cudaGetSymbolAddress(&p_w3l,  d_w3l);
    cudaGetSymbolAddress(&p_wsnh, d_wsnh);
    cudaGetSymbolAddress(&p_wsnl, d_wsnl);

    // phase 1: mlp || w3 split || wsn split
    phase1_kernel<<<768, 256>>>(x, w1, b1, w2, b2, w3, wsn1);

    // phase 2: knn64 || knn3 || precomp64
    phase2_kernel<<<1172, 256, KM_SMEM>>>(x, wdg1, bdg1);

    edge2_kernel<<<148, 256, E2_SMEM>>>(
        (const float*)p_A1, (const float*)p_C1, (const int*)p_idx1, wdg2, bdg2,
        (__nv_bfloat16*)p_cath, (__nv_bfloat16*)p_catl);

    precomp_mma_kernel<<<dim3(NP/128, 4), 256, FG_SMEM>>>(
        (const __nv_bfloat16*)p_cath, (const __nv_bfloat16*)p_catl,
        (const __nv_bfloat16*)p_wsnh, (const __nv_bfloat16*)p_wsnl,
        bsn1, (float*)p_A3, (float*)p_C3);

    edge3_kernel<<<512, 256>>>((const float*)p_A3, (const float*)p_C3, (const int*)p_idx2,
        (__nv_bfloat16*)p_cath, (__nv_bfloat16*)p_catl);

    fgemm_mma_kernel<<<dim3(NP/128, 8), 256, FG_SMEM>>>(
        (const __nv_bfloat16*)p_cath, (const __nv_bfloat16*)p_catl,
        (const __nv_bfloat16*)p_w3h,  (const __nv_bfloat16*)p_w3l, b3, out);
}